// round 9
// baseline (speedup 1.0000x reference)
#include <cuda_runtime.h>
#include <cuda_bf16.h>
#include <math.h>
#include <stdint.h>

// Problem constants
#define BB   16
#define HH   56
#define WW   56
#define CC   96
#define LL_  3136        // 56*56
#define NHD  3
#define WS_  7
#define TT   49
#define HID_ 384
#define NCL_ 128
#define TWOH 768
#define NTOT (BB * LL_)  // 50176 tokens

#define LOG_EPS -13.815511f   // log(1e-6)

// ---------------------------------------------------------------------------
// device-global scratch (no allocation allowed)
// ---------------------------------------------------------------------------
__device__ float d_x1[NTOT * CC];                       // residual after attention
__device__ __nv_bfloat16 d_llh[(size_t)NTOT * TWOH];    // loglit hi (bf16)
__device__ __nv_bfloat16 d_llo[(size_t)NTOT * TWOH];    // loglit lo (bf16)
__device__ uint4 d_maskF[12 * 4 * 8 * 32];              // pre-fragmented mask B operands
__device__ float d_pinT[CC * HID_];                     // pin_w^T [c][h]
__device__ float d_qkvT[CC * 288];                      // qkv_w^T [c][o]
__device__ float d_projT[CC * CC];                      // proj_w^T [c][o]

// ---------------------------------------------------------------------------
// helpers
// ---------------------------------------------------------------------------
__device__ __forceinline__ uint32_t smem_u32(const void* p) {
    uint32_t a;
    asm("{ .reg .u64 t; cvta.to.shared.u64 t, %1; cvt.u32.u64 %0, t; }" : "=r"(a) : "l"(p));
    return a;
}

#define CP16(dst, src) \
    asm volatile("cp.async.cg.shared.global [%0], [%1], 16;" \
                 :: "r"(dst), "l"(src) : "memory")

#define LDMX4(r, a) \
    asm volatile("ldmatrix.sync.aligned.m8n8.x4.shared.b16 {%0,%1,%2,%3}, [%4];" \
                 : "=r"((r)[0]), "=r"((r)[1]), "=r"((r)[2]), "=r"((r)[3]) : "r"(a))

__device__ __forceinline__ void mma16816(float* d, uint32_t a0, uint32_t a1,
                                         uint32_t a2, uint32_t a3,
                                         uint32_t b0, uint32_t b1) {
    asm volatile(
        "mma.sync.aligned.m16n8k16.row.col.f32.bf16.bf16.f32 "
        "{%0,%1,%2,%3}, {%4,%5,%6,%7}, {%8,%9}, {%0,%1,%2,%3};"
        : "+f"(d[0]), "+f"(d[1]), "+f"(d[2]), "+f"(d[3])
        : "r"(a0), "r"(a1), "r"(a2), "r"(a3), "r"(b0), "r"(b1));
}

__device__ __forceinline__ unsigned bmask_bits(float v) {
    return v > 0.0f ? 0x3F80u : 0u;   // bf16 1.0 / 0.0
}

// ---------------------------------------------------------------------------
// Prep: pre-fragment binarized mask for mma B operands; transpose weights.
// maskF entry e: lane=e&31, ntp=(e>>5)&7, ks=(e>>8)&3, ch=e>>10.
// For warp fragment (n = nt*8 + lane/4, k = ch*64+ks*16+(lane%4)*2):
//   u.x/u.y = b0/b1 for nt=2*ntp; u.z/u.w = b0/b1 for nt=2*ntp+1.
// ---------------------------------------------------------------------------
__global__ void prep_kernel(const float* __restrict__ tm_inc,
                            const float* __restrict__ pin_w,
                            const float* __restrict__ qkv_w,
                            const float* __restrict__ proj_w) {
    int i = blockIdx.x * 256 + threadIdx.x;
    if (i < 12288) {
        int lane = i & 31, ntp = (i >> 5) & 7, ks = (i >> 8) & 3, ch = i >> 10;
        int qr = lane >> 2;
        int k  = ch * 64 + ks * 16 + (lane & 3) * 2;
        int n0 = ntp * 16 + qr, n1 = n0 + 8;
        const float* p0 = tm_inc + n0 * TWOH;
        const float* p1 = tm_inc + n1 * TWOH;
        uint4 u;
        u.x = bmask_bits(p0[k])     | (bmask_bits(p0[k + 1]) << 16);
        u.y = bmask_bits(p0[k + 8]) | (bmask_bits(p0[k + 9]) << 16);
        u.z = bmask_bits(p1[k])     | (bmask_bits(p1[k + 1]) << 16);
        u.w = bmask_bits(p1[k + 8]) | (bmask_bits(p1[k + 9]) << 16);
        d_maskF[i] = u;
        return;
    }
    i -= 12288;
    if (i < HID_ * CC) {
        int h = i / CC, c = i - h * CC;
        d_pinT[c * HID_ + h] = pin_w[i];
        return;
    }
    i -= HID_ * CC;
    if (i < 288 * CC) {
        int o = i / CC, c = i - o * CC;
        d_qkvT[c * 288 + o] = qkv_w[i];
        return;
    }
    i -= 288 * CC;
    if (i < CC * CC) {
        int o = i / CC, c = i - o * CC;
        d_projT[c * CC + o] = proj_w[i];
    }
}

// ---------------------------------------------------------------------------
// Kernel 1: fused window attention (unchanged — 4x4 register tiles)
// ---------------------------------------------------------------------------
#define TP 52
#define AT_SZ  (96 * TP)
#define QT_SZ  (96 * TP)
#define KT_SZ  (96 * TP)
#define V_STR  100
#define V_SZ   (TP * V_STR)
#define S3_SZ  (3 * 49 * 49)
#define ATTN_SMEM ((AT_SZ + QT_SZ + KT_SZ + V_SZ + S3_SZ) * 4)

__global__ __launch_bounds__(256)
void attn_kernel(const float* __restrict__ x,
                 const float* __restrict__ n1g, const float* __restrict__ n1b,
                 const float* __restrict__ qkv_b,
                 const float* __restrict__ proj_b) {
    extern __shared__ float sm[];
    float* AT = sm;
    float* QT = AT + AT_SZ;
    float* KT = QT + QT_SZ;
    float* V  = KT + KT_SZ;
    float* S3 = V + V_SZ;

    const int tid  = threadIdx.x;
    const int lane = tid & 31;
    const int warp = tid >> 5;
    const int bw = blockIdx.x;
    const int b  = bw >> 6;
    const int wi = (bw >> 3) & 7;
    const int wj = bw & 7;

    for (int t = warp; t < TT; t += 8) {
        int ti = t / WS_, tj = t - ti * WS_;
        int r = (wi * WS_ + ti + 3) % HH;
        int c = (wj * WS_ + tj + 3) % WW;
        const float* row = x + ((size_t)(b * LL_ + r * WW + c)) * CC;
        float v0 = row[lane], v1 = row[lane + 32], v2 = row[lane + 64];
        float s = v0 + v1 + v2;
        #pragma unroll
        for (int o = 16; o; o >>= 1) s += __shfl_xor_sync(~0u, s, o);
        float m = s * (1.0f / 96.0f);
        float d0 = v0 - m, d1 = v1 - m, d2 = v2 - m;
        float vv = d0 * d0 + d1 * d1 + d2 * d2;
        #pragma unroll
        for (int o = 16; o; o >>= 1) vv += __shfl_xor_sync(~0u, vv, o);
        float inv = rsqrtf(vv * (1.0f / 96.0f) + 1e-5f);
        AT[lane * TP + t]        = d0 * inv * n1g[lane]      + n1b[lane];
        AT[(lane + 32) * TP + t] = d1 * inv * n1g[lane + 32] + n1b[lane + 32];
        AT[(lane + 64) * TP + t] = d2 * inv * n1g[lane + 64] + n1b[lane + 64];
    }
    __syncthreads();

    for (int idx = tid; idx < 13 * 72; idx += 256) {
        int og = idx % 72, tg = idx / 72;
        int o = og * 4;
        float a[4][4];
        #pragma unroll
        for (int ii = 0; ii < 4; ii++)
            #pragma unroll
            for (int k = 0; k < 4; k++) a[ii][k] = 0.0f;
        const float* atb = &AT[tg * 4];
        #pragma unroll 4
        for (int c = 0; c < CC; c++) {
            float4 av = *reinterpret_cast<const float4*>(&atb[c * TP]);
            float4 wv = *reinterpret_cast<const float4*>(&d_qkvT[c * 288 + o]);
            float avv[4] = {av.x, av.y, av.z, av.w};
            float wvv[4] = {wv.x, wv.y, wv.z, wv.w};
            #pragma unroll
            for (int ii = 0; ii < 4; ii++)
                #pragma unroll
                for (int k = 0; k < 4; k++) a[ii][k] += avv[ii] * wvv[k];
        }
        #pragma unroll
        for (int k = 0; k < 4; k++) {
            int ok = o + k;
            float bias = qkv_b[ok];
            #pragma unroll
            for (int ii = 0; ii < 4; ii++) {
                int t = tg * 4 + ii;
                float v = a[ii][k] + bias;
                if (ok < 96)       QT[ok * TP + t] = v;
                else if (ok < 192) KT[(ok - 96) * TP + t] = v;
                else               V[t * V_STR + (ok - 192)] = v;
            }
        }
    }
    __syncthreads();

    for (int idx = tid; idx < 507; idx += 256) {
        int h = idx / 169; int r = idx - h * 169;
        int ig = r / 13, jg = r - (r / 13) * 13;
        float a[4][4];
        #pragma unroll
        for (int ii = 0; ii < 4; ii++)
            #pragma unroll
            for (int jj = 0; jj < 4; jj++) a[ii][jj] = 0.0f;
        const float* qb = &QT[h * 32 * TP + ig * 4];
        const float* kb = &KT[h * 32 * TP + jg * 4];
        #pragma unroll 8
        for (int d = 0; d < 32; d++) {
            float4 qv = *reinterpret_cast<const float4*>(&qb[d * TP]);
            float4 kv = *reinterpret_cast<const float4*>(&kb[d * TP]);
            float qq[4] = {qv.x, qv.y, qv.z, qv.w};
            float kk[4] = {kv.x, kv.y, kv.z, kv.w};
            #pragma unroll
            for (int ii = 0; ii < 4; ii++)
                #pragma unroll
                for (int jj = 0; jj < 4; jj++) a[ii][jj] += qq[ii] * kk[jj];
        }
        #pragma unroll
        for (int ii = 0; ii < 4; ii++) {
            int i = ig * 4 + ii;
            if (i < TT) {
                #pragma unroll
                for (int jj = 0; jj < 4; jj++) {
                    int j = jg * 4 + jj;
                    if (j < TT)
                        S3[h * (TT * TT) + i * TT + j] = a[ii][jj] * 0.17677669529663687f;
                }
            }
        }
    }
    __syncthreads();

    for (int row = warp; row < 3 * TT; row += 8) {
        float* Sr = &S3[row * TT];
        float a0 = Sr[lane];
        float a1 = (lane < 17) ? Sr[32 + lane] : -1e30f;
        float mx = fmaxf(a0, a1);
        #pragma unroll
        for (int o = 16; o; o >>= 1) mx = fmaxf(mx, __shfl_xor_sync(~0u, mx, o));
        float e0 = __expf(a0 - mx);
        float e1 = (lane < 17) ? __expf(a1 - mx) : 0.0f;
        float ss = e0 + e1;
        #pragma unroll
        for (int o = 16; o; o >>= 1) ss += __shfl_xor_sync(~0u, ss, o);
        float inv = __fdividef(1.0f, ss);
        Sr[lane] = e0 * inv;
        if (lane < 17) Sr[32 + lane] = e1 * inv;
    }
    __syncthreads();

    for (int idx = tid; idx < 312; idx += 256) {
        int h = idx / 104; int r = idx - h * 104;
        int ig = r >> 3, dg = r & 7;
        float a[4][4];
        #pragma unroll
        for (int ii = 0; ii < 4; ii++)
            #pragma unroll
            for (int k = 0; k < 4; k++) a[ii][k] = 0.0f;
        const float* S0 = &S3[h * (TT * TT) + min(ig * 4 + 0, 48) * TT];
        const float* S1 = &S3[h * (TT * TT) + min(ig * 4 + 1, 48) * TT];
        const float* S2 = &S3[h * (TT * TT) + min(ig * 4 + 2, 48) * TT];
        const float* Sx = &S3[h * (TT * TT) + min(ig * 4 + 3, 48) * TT];
        const float* Vb = &V[h * 32 + dg * 4];
        #pragma unroll 7
        for (int j = 0; j < TT; j++) {
            float4 vv = *reinterpret_cast<const float4*>(&Vb[j * V_STR]);
            float vvv[4] = {vv.x, vv.y, vv.z, vv.w};
            float ss[4] = {S0[j], S1[j], S2[j], Sx[j]};
            #pragma unroll
            for (int ii = 0; ii < 4; ii++)
                #pragma unroll
                for (int k = 0; k < 4; k++) a[ii][k] += ss[ii] * vvv[k];
        }
        #pragma unroll
        for (int k = 0; k < 4; k++)
            #pragma unroll
            for (int ii = 0; ii < 4; ii++)
                AT[(h * 32 + dg * 4 + k) * TP + ig * 4 + ii] = a[ii][k];
    }
    __syncthreads();

    for (int idx = tid; idx < 312; idx += 256) {
        int tg = idx % 13, cg = idx / 13;
        int co = cg * 4;
        float a[4][4];
        #pragma unroll
        for (int ii = 0; ii < 4; ii++)
            #pragma unroll
            for (int k = 0; k < 4; k++) a[ii][k] = 0.0f;
        const float* atb = &AT[tg * 4];
        #pragma unroll 4
        for (int c = 0; c < CC; c++) {
            float4 ov = *reinterpret_cast<const float4*>(&atb[c * TP]);
            float4 wv = *reinterpret_cast<const float4*>(&d_projT[c * CC + co]);
            float oo[4] = {ov.x, ov.y, ov.z, ov.w};
            float ww[4] = {wv.x, wv.y, wv.z, wv.w};
            #pragma unroll
            for (int ii = 0; ii < 4; ii++)
                #pragma unroll
                for (int k = 0; k < 4; k++) a[ii][k] += oo[ii] * ww[k];
        }
        #pragma unroll
        for (int ii = 0; ii < 4; ii++) {
            int t = tg * 4 + ii;
            if (t < TT) {
                int ti = t / WS_, tj = t - ti * WS_;
                int dr = wi * WS_ + (ti + 3) % WS_;
                int dc = wj * WS_ + (tj + 3) % WS_;
                size_t off = ((size_t)(b * LL_ + dr * WW + dc)) * CC + co;
                float4 xr = *reinterpret_cast<const float4*>(&x[off]);
                float4 res = make_float4(xr.x + a[ii][0] + proj_b[co],
                                         xr.y + a[ii][1] + proj_b[co + 1],
                                         xr.z + a[ii][2] + proj_b[co + 2],
                                         xr.w + a[ii][3] + proj_b[co + 3]);
                *reinterpret_cast<float4*>(&d_x1[off]) = res;
            }
        }
    }
}

// ---------------------------------------------------------------------------
// Kernel 2: pin stage. 16 tokens / CTA, 128 threads. LN2 -> LN_ffn ->
// pin GEMM -> softplus loglits -> separate hi/lo bf16 arrays.
// ---------------------------------------------------------------------------
#define TB 16
#define PIN_SMEM (96 * TB * 4)

__global__ __launch_bounds__(128)
void pin_kernel(const float* __restrict__ n2g, const float* __restrict__ n2b,
                const float* __restrict__ nfg, const float* __restrict__ nfb,
                const float* __restrict__ pin_b) {
    extern __shared__ float smw[];
    float* WT = smw;                  // [96][16]

    const int tid  = threadIdx.x;
    const int lane = tid & 31;
    const int warp = tid >> 5;
    const int tg4  = (tid & 3) * 4;
    const size_t t0 = (size_t)blockIdx.x * TB;

    for (int tt = warp; tt < TB; tt += 4) {
        const float* row = d_x1 + (t0 + tt) * CC;
        float v0 = row[lane], v1 = row[lane + 32], v2 = row[lane + 64];
        float s = v0 + v1 + v2;
        #pragma unroll
        for (int o = 16; o; o >>= 1) s += __shfl_xor_sync(~0u, s, o);
        float m = s * (1.0f / 96.0f);
        float d0 = v0 - m, d1 = v1 - m, d2 = v2 - m;
        float vv = d0 * d0 + d1 * d1 + d2 * d2;
        #pragma unroll
        for (int o = 16; o; o >>= 1) vv += __shfl_xor_sync(~0u, vv, o);
        float inv = rsqrtf(vv * (1.0f / 96.0f) + 1e-5f);
        float z0 = d0 * inv * n2g[lane]      + n2b[lane];
        float z1 = d1 * inv * n2g[lane + 32] + n2b[lane + 32];
        float z2 = d2 * inv * n2g[lane + 64] + n2b[lane + 64];
        float s2 = z0 + z1 + z2;
        #pragma unroll
        for (int o = 16; o; o >>= 1) s2 += __shfl_xor_sync(~0u, s2, o);
        float m2 = s2 * (1.0f / 96.0f);
        float e0 = z0 - m2, e1 = z1 - m2, e2 = z2 - m2;
        float v2s = e0 * e0 + e1 * e1 + e2 * e2;
        #pragma unroll
        for (int o = 16; o; o >>= 1) v2s += __shfl_xor_sync(~0u, v2s, o);
        float inv2 = rsqrtf(v2s * (1.0f / 96.0f) + 1e-5f);
        WT[lane * TB + tt]        = e0 * inv2 * nfg[lane]      + nfb[lane];
        WT[(lane + 32) * TB + tt] = e1 * inv2 * nfg[lane + 32] + nfb[lane + 32];
        WT[(lane + 64) * TB + tt] = e2 * inv2 * nfg[lane + 64] + nfb[lane + 64];
    }
    __syncthreads();

    for (int hg = tid >> 2; hg < HID_ / 4; hg += 32) {
        int h = hg * 4;
        float a[4][4];
        #pragma unroll
        for (int ii = 0; ii < 4; ii++)
            #pragma unroll
            for (int k = 0; k < 4; k++) a[ii][k] = 0.0f;
        #pragma unroll 8
        for (int c = 0; c < CC; c++) {
            float4 wv = *reinterpret_cast<const float4*>(&WT[c * TB + tg4]);
            float4 p  = *reinterpret_cast<const float4*>(&d_pinT[c * HID_ + h]);
            float ww[4] = {wv.x, wv.y, wv.z, wv.w};
            float pp[4] = {p.x, p.y, p.z, p.w};
            #pragma unroll
            for (int ii = 0; ii < 4; ii++)
                #pragma unroll
                for (int k = 0; k < 4; k++) a[ii][k] += ww[ii] * pp[k];
        }
        float bias[4] = {pin_b[h], pin_b[h + 1], pin_b[h + 2], pin_b[h + 3]};
        #pragma unroll
        for (int ii = 0; ii < 4; ii++) {
            unsigned hh[4], ll[4];
            #pragma unroll
            for (int k = 0; k < 4; k++) {
                float v = a[ii][k] + bias[k];
                // log(sig(v)) = -softplus(-v);  log(1-sig(v)) = -softplus(v)
                float spn = (v < -15.f) ? -v : __logf(1.0f + __expf(-v));
                float spp = (v >  15.f) ?  v : __logf(1.0f + __expf(v));
                float l1 = fmaxf(-spn, LOG_EPS);
                float l2 = fmaxf(-spp, LOG_EPS);
                __nv_bfloat16 h1 = __float2bfloat16(l1);
                __nv_bfloat16 h2 = __float2bfloat16(l2);
                __nv_bfloat16 o1 = __float2bfloat16(l1 - __bfloat162float(h1));
                __nv_bfloat16 o2 = __float2bfloat16(l2 - __bfloat162float(h2));
                hh[k] = (unsigned)__bfloat16_as_ushort(h1) |
                        ((unsigned)__bfloat16_as_ushort(h2) << 16);
                ll[k] = (unsigned)__bfloat16_as_ushort(o1) |
                        ((unsigned)__bfloat16_as_ushort(o2) << 16);
            }
            size_t t = t0 + tg4 + ii;
            // hh[k] holds (pos, neg) for one hidden unit: pos at h+k, neg at h+k+HID_
            #pragma unroll
            for (int k = 0; k < 4; k++) {
                __nv_bfloat16* ph = &d_llh[t * TWOH + h + k];
                __nv_bfloat16* pl = &d_llo[t * TWOH + h + k];
                ph[0]    = __ushort_as_bfloat16((unsigned short)(hh[k] & 0xffff));
                ph[HID_] = __ushort_as_bfloat16((unsigned short)(hh[k] >> 16));
                pl[0]    = __ushort_as_bfloat16((unsigned short)(ll[k] & 0xffff));
                pl[HID_] = __ushort_as_bfloat16((unsigned short)(ll[k] >> 16));
            }
        }
    }
}

// ---------------------------------------------------------------------------
// Kernel 3: clause GEMM, 64 tokens / CTA (784 CTAs), 128 threads (4 warps).
// cp.async double-buffered loglit staging; ldmatrix A frags; mask B frags
// via coalesced LDG.128 from pre-fragmented gmem. Epilogue: exp -> CLT ->
// fp32 tm_out GEMM -> gated blend + residual.
// ---------------------------------------------------------------------------
#define NTOK 64
#define BUF_SZ 18432                        // hi(9216) + lo(9216) per buffer
#define CLT_STR 68
#define CLA_SMEM (2 * BUF_SZ)               // 36864; CLT (34816) overlays

__global__ __launch_bounds__(128)
void clause_kernel(const float* __restrict__ tm_out,
                   const float* __restrict__ gate,
                   float* __restrict__ out) {
    extern __shared__ char smc[];
    const uint32_t sb = smem_u32(smc);
    float* CLT = reinterpret_cast<float*>(smc);

    const int tid  = threadIdx.x;
    const int wid  = tid >> 5;
    const int lane = tid & 31;
    const int qr   = lane >> 2;
    const int qc   = (lane & 3) * 2;
    const int t0   = blockIdx.x * NTOK;
    const int r0   = wid * 16;

    float acc[64];
    #pragma unroll
    for (int i = 0; i < 64; i++) acc[i] = 0.0f;

    // stage chunk 0 into buffer 0
    {
        const __nv_bfloat16* __restrict__ bh = d_llh + (size_t)t0 * TWOH;
        const __nv_bfloat16* __restrict__ bl = d_llo + (size_t)t0 * TWOH;
        for (int idx = tid; idx < 1024; idx += 128) {
            int half = idx >> 9;
            int row  = (idx >> 3) & 63;
            int col  = idx & 7;
            const __nv_bfloat16* src =
                (half ? bl : bh) + (size_t)row * TWOH + col * 8;
            uint32_t dst = sb + half * 9216 + row * 144 + col * 16;
            CP16(dst, src);
        }
        asm volatile("cp.async.commit_group;" ::: "memory");
    }

    for (int ch = 0; ch < 12; ch++) {
        asm volatile("cp.async.wait_group 0;" ::: "memory");
        __syncthreads();
        if (ch < 11) {
            const int nb = (ch + 1) & 1;
            const int ko = (ch + 1) * 64;
            const __nv_bfloat16* __restrict__ bh = d_llh + (size_t)t0 * TWOH + ko;
            const __nv_bfloat16* __restrict__ bl = d_llo + (size_t)t0 * TWOH + ko;
            for (int idx = tid; idx < 1024; idx += 128) {
                int half = idx >> 9;
                int row  = (idx >> 3) & 63;
                int col  = idx & 7;
                const __nv_bfloat16* src =
                    (half ? bl : bh) + (size_t)row * TWOH + col * 8;
                uint32_t dst = sb + nb * BUF_SZ + half * 9216 + row * 144 + col * 16;
                CP16(dst, src);
            }
            asm volatile("cp.async.commit_group;" ::: "memory");
        }

        const uint32_t bufb = sb + (ch & 1) * BUF_SZ;
        const uint32_t arow = r0 + (lane & 7) + ((lane >> 3) & 1) * 8;
        const uint32_t abase = bufb + arow * 144 + ((lane >> 4) * 8) * 2;
        #pragma unroll
        for (int ks = 0; ks < 4; ks++) {
            uint32_t ah[4], al[4];
            uint32_t addr = abase + ks * 32;
            LDMX4(ah, addr);
            LDMX4(al, addr + 9216);
            const uint4* __restrict__ mf = d_maskF + ((ch * 4 + ks) * 8) * 32 + lane;
            #pragma unroll
            for (int ntp = 0; ntp < 8; ntp++) {
                uint4 b = mf[ntp * 32];
                mma16816(&acc[(2 * ntp) * 4],     ah[0], ah[1], ah[2], ah[3], b.x, b.y);
                mma16816(&acc[(2 * ntp) * 4],     al[0], al[1], al[2], al[3], b.x, b.y);
                mma16816(&acc[(2 * ntp + 1) * 4], ah[0], ah[1], ah[2], ah[3], b.z, b.w);
                mma16816(&acc[(2 * ntp + 1) * 4], al[0], al[1], al[2], al[3], b.z, b.w);
            }
        }
    }
    __syncthreads();   // staging buffers dead; CLT overlays

    // exp + transposed store: CLT[j][t_local]
    #pragma unroll
    for (int nt = 0; nt < 16; nt++) {
        int j = nt * 8 + qc;
        CLT[j * CLT_STR + r0 + qr]           = __expf(acc[nt * 4 + 0]);
        CLT[(j + 1) * CLT_STR + r0 + qr]     = __expf(acc[nt * 4 + 1]);
        CLT[j * CLT_STR + r0 + qr + 8]       = __expf(acc[nt * 4 + 2]);
        CLT[(j + 1) * CLT_STR + r0 + qr + 8] = __expf(acc[nt * 4 + 3]);
    }
    __syncthreads();

    // logits = clauses @ tm_out; gated blend + residual
    const float g = __fdividef(1.0f, 1.0f + __expf(-gate[0]));
    for (int idx = tid; idx < 16 * 24; idx += 128) {
        int tg = idx & 15, cg = idx >> 4;
        float a[4][4];
        #pragma unroll
        for (int ii = 0; ii < 4; ii++)
            #pragma unroll
            for (int k = 0; k < 4; k++) a[ii][k] = 0.0f;
        const float* clb = &CLT[tg * 4];
        const float* ob  = &tm_out[cg * 4];
        #pragma unroll 8
        for (int j = 0; j < NCL_; j++) {
            float4 cv = *reinterpret_cast<const float4*>(&clb[j * CLT_STR]);
            float4 ov = *reinterpret_cast<const float4*>(&ob[j * CC]);
            float cc[4] = {cv.x, cv.y, cv.z, cv.w};
            float oo[4] = {ov.x, ov.y, ov.z, ov.w};
            #pragma unroll
            for (int ii = 0; ii < 4; ii++)
                #pragma unroll
                for (int k = 0; k < 4; k++) a[ii][k] += cc[ii] * oo[k];
        }
        #pragma unroll
        for (int ii = 0; ii < 4; ii++) {
            size_t off = (size_t)(t0 + tg * 4 + ii) * CC + cg * 4;
            float4 xr = *reinterpret_cast<const float4*>(&d_x1[off]);
            float r[4];
            #pragma unroll
            for (int k = 0; k < 4; k++) {
                float lg = a[ii][k];
                float sg = __fdividef(1.0f, 1.0f + __expf(-lg));
                r[k] = g * lg + (1.0f - g) * sg;
            }
            float4 res = make_float4(xr.x + r[0], xr.y + r[1], xr.z + r[2], xr.w + r[3]);
            *reinterpret_cast<float4*>(&out[off]) = res;
        }
    }
}

// ---------------------------------------------------------------------------
extern "C" void kernel_launch(void* const* d_in, const int* in_sizes, int n_in,
                              void* d_out, int out_size) {
    (void)in_sizes; (void)n_in; (void)out_size;
    const float* x      = (const float*)d_in[0];
    const float* n1g    = (const float*)d_in[1];
    const float* n1b    = (const float*)d_in[2];
    const float* qkv_w  = (const float*)d_in[3];
    const float* qkv_b  = (const float*)d_in[4];
    const float* proj_w = (const float*)d_in[5];
    const float* proj_b = (const float*)d_in[6];
    const float* n2g    = (const float*)d_in[7];
    const float* n2b    = (const float*)d_in[8];
    const float* nfg    = (const float*)d_in[9];
    const float* nfb    = (const float*)d_in[10];
    const float* pin_w  = (const float*)d_in[11];
    const float* pin_b  = (const float*)d_in[12];
    const float* tm_inc = (const float*)d_in[13];
    const float* tm_out = (const float*)d_in[14];
    const float* gate   = (const float*)d_in[15];
    float* out = (float*)d_out;

    cudaFuncSetAttribute(attn_kernel,   cudaFuncAttributeMaxDynamicSharedMemorySize, ATTN_SMEM);
    cudaFuncSetAttribute(clause_kernel, cudaFuncAttributeMaxDynamicSharedMemorySize, CLA_SMEM);

    // prep covers 12288 + 36864 + 27648 + 9216 = 86016 = 336 * 256
    prep_kernel<<<336, 256>>>(tm_inc, pin_w, qkv_w, proj_w);
    attn_kernel<<<BB * 64, 256, ATTN_SMEM>>>(x, n1g, n1b, qkv_b, proj_b);
    pin_kernel<<<NTOT / TB, 128, PIN_SMEM>>>(n2g, n2b, nfg, nfb, pin_b);
    clause_kernel<<<NTOT / NTOK, 128, CLA_SMEM>>>(tm_out, gate, out);
}

// round 11
// speedup vs baseline: 1.0415x; 1.0415x over previous
#include <cuda_runtime.h>
#include <cuda_bf16.h>
#include <math.h>
#include <stdint.h>

// Problem constants
#define BB   16
#define HH   56
#define WW   56
#define CC   96
#define LL_  3136        // 56*56
#define NHD  3
#define WS_  7
#define TT   49
#define HID_ 384
#define NCL_ 128
#define TWOH 768
#define NTOT (BB * LL_)  // 50176 tokens

#define LOG_EPS -13.815511f   // log(1e-6)

// ---------------------------------------------------------------------------
// device-global scratch (no allocation allowed)
// ---------------------------------------------------------------------------
__device__ float d_x1[NTOT * CC];                  // residual after attention
__device__ unsigned int d_ll[(size_t)NTOT * TWOH]; // packed loglits: hi | lo<<16 (bf16)
__device__ uint4 d_maskF[12 * 4 * 8 * 32];         // pre-fragmented mask B operands
__device__ float d_pinT[CC * HID_];                // pin_w^T [c][h]
__device__ float d_qkvT[CC * 288];                 // qkv_w^T [c][o]
__device__ float d_projT[CC * CC];                 // proj_w^T [c][o]

// ---------------------------------------------------------------------------
// helpers
// ---------------------------------------------------------------------------
__device__ __forceinline__ uint32_t smem_u32(const void* p) {
    uint32_t a;
    asm("{ .reg .u64 t; cvta.to.shared.u64 t, %1; cvt.u32.u64 %0, t; }" : "=r"(a) : "l"(p));
    return a;
}

#define LDMX4(r, a) \
    asm volatile("ldmatrix.sync.aligned.m8n8.x4.shared.b16 {%0,%1,%2,%3}, [%4];" \
                 : "=r"((r)[0]), "=r"((r)[1]), "=r"((r)[2]), "=r"((r)[3]) : "r"(a))

__device__ __forceinline__ void mma16816(float* d, uint32_t a0, uint32_t a1,
                                         uint32_t a2, uint32_t a3,
                                         uint32_t b0, uint32_t b1) {
    asm volatile(
        "mma.sync.aligned.m16n8k16.row.col.f32.bf16.bf16.f32 "
        "{%0,%1,%2,%3}, {%4,%5,%6,%7}, {%8,%9}, {%0,%1,%2,%3};"
        : "+f"(d[0]), "+f"(d[1]), "+f"(d[2]), "+f"(d[3])
        : "r"(a0), "r"(a1), "r"(a2), "r"(a3), "r"(b0), "r"(b1));
}

__device__ __forceinline__ unsigned bmask_bits(float v) {
    return v > 0.0f ? 0x3F80u : 0u;   // bf16 1.0 / 0.0
}

__device__ __forceinline__ unsigned pack_ll(float l) {
    __nv_bfloat16 h = __float2bfloat16(l);
    __nv_bfloat16 lo = __float2bfloat16(l - __bfloat162float(h));
    return (unsigned)__bfloat16_as_ushort(h) | ((unsigned)__bfloat16_as_ushort(lo) << 16);
}

// ---------------------------------------------------------------------------
// Prep: pre-fragment binarized mask for mma B operands; transpose weights.
// ---------------------------------------------------------------------------
__global__ void prep_kernel(const float* __restrict__ tm_inc,
                            const float* __restrict__ pin_w,
                            const float* __restrict__ qkv_w,
                            const float* __restrict__ proj_w) {
    int i = blockIdx.x * 256 + threadIdx.x;
    if (i < 12288) {
        int lane = i & 31, ntp = (i >> 5) & 7, ks = (i >> 8) & 3, ch = i >> 10;
        int qr = lane >> 2;
        int k  = ch * 64 + ks * 16 + (lane & 3) * 2;
        int n0 = ntp * 16 + qr, n1 = n0 + 8;
        const float* p0 = tm_inc + n0 * TWOH;
        const float* p1 = tm_inc + n1 * TWOH;
        uint4 u;
        u.x = bmask_bits(p0[k])     | (bmask_bits(p0[k + 1]) << 16);
        u.y = bmask_bits(p0[k + 8]) | (bmask_bits(p0[k + 9]) << 16);
        u.z = bmask_bits(p1[k])     | (bmask_bits(p1[k + 1]) << 16);
        u.w = bmask_bits(p1[k + 8]) | (bmask_bits(p1[k + 9]) << 16);
        d_maskF[i] = u;
        return;
    }
    i -= 12288;
    if (i < HID_ * CC) {
        int h = i / CC, c = i - h * CC;
        d_pinT[c * HID_ + h] = pin_w[i];
        return;
    }
    i -= HID_ * CC;
    if (i < 288 * CC) {
        int o = i / CC, c = i - o * CC;
        d_qkvT[c * 288 + o] = qkv_w[i];
        return;
    }
    i -= 288 * CC;
    if (i < CC * CC) {
        int o = i / CC, c = i - o * CC;
        d_projT[c * CC + o] = proj_w[i];
    }
}

// ---------------------------------------------------------------------------
// Kernel 1: fused window attention (unchanged — 4x4 register tiles)
// ---------------------------------------------------------------------------
#define TP 52
#define AT_SZ  (96 * TP)
#define QT_SZ  (96 * TP)
#define KT_SZ  (96 * TP)
#define V_STR  100
#define V_SZ   (TP * V_STR)
#define S3_SZ  (3 * 49 * 49)
#define ATTN_SMEM ((AT_SZ + QT_SZ + KT_SZ + V_SZ + S3_SZ) * 4)

__global__ __launch_bounds__(256)
void attn_kernel(const float* __restrict__ x,
                 const float* __restrict__ n1g, const float* __restrict__ n1b,
                 const float* __restrict__ qkv_b,
                 const float* __restrict__ proj_b) {
    extern __shared__ float sm[];
    float* AT = sm;
    float* QT = AT + AT_SZ;
    float* KT = QT + QT_SZ;
    float* V  = KT + KT_SZ;
    float* S3 = V + V_SZ;

    const int tid  = threadIdx.x;
    const int lane = tid & 31;
    const int warp = tid >> 5;
    const int bw = blockIdx.x;
    const int b  = bw >> 6;
    const int wi = (bw >> 3) & 7;
    const int wj = bw & 7;

    for (int t = warp; t < TT; t += 8) {
        int ti = t / WS_, tj = t - ti * WS_;
        int r = (wi * WS_ + ti + 3) % HH;
        int c = (wj * WS_ + tj + 3) % WW;
        const float* row = x + ((size_t)(b * LL_ + r * WW + c)) * CC;
        float v0 = row[lane], v1 = row[lane + 32], v2 = row[lane + 64];
        float s = v0 + v1 + v2;
        #pragma unroll
        for (int o = 16; o; o >>= 1) s += __shfl_xor_sync(~0u, s, o);
        float m = s * (1.0f / 96.0f);
        float d0 = v0 - m, d1 = v1 - m, d2 = v2 - m;
        float vv = d0 * d0 + d1 * d1 + d2 * d2;
        #pragma unroll
        for (int o = 16; o; o >>= 1) vv += __shfl_xor_sync(~0u, vv, o);
        float inv = rsqrtf(vv * (1.0f / 96.0f) + 1e-5f);
        AT[lane * TP + t]        = d0 * inv * n1g[lane]      + n1b[lane];
        AT[(lane + 32) * TP + t] = d1 * inv * n1g[lane + 32] + n1b[lane + 32];
        AT[(lane + 64) * TP + t] = d2 * inv * n1g[lane + 64] + n1b[lane + 64];
    }
    __syncthreads();

    for (int idx = tid; idx < 13 * 72; idx += 256) {
        int og = idx % 72, tg = idx / 72;
        int o = og * 4;
        float a[4][4];
        #pragma unroll
        for (int ii = 0; ii < 4; ii++)
            #pragma unroll
            for (int k = 0; k < 4; k++) a[ii][k] = 0.0f;
        const float* atb = &AT[tg * 4];
        #pragma unroll 4
        for (int c = 0; c < CC; c++) {
            float4 av = *reinterpret_cast<const float4*>(&atb[c * TP]);
            float4 wv = *reinterpret_cast<const float4*>(&d_qkvT[c * 288 + o]);
            float avv[4] = {av.x, av.y, av.z, av.w};
            float wvv[4] = {wv.x, wv.y, wv.z, wv.w};
            #pragma unroll
            for (int ii = 0; ii < 4; ii++)
                #pragma unroll
                for (int k = 0; k < 4; k++) a[ii][k] += avv[ii] * wvv[k];
        }
        #pragma unroll
        for (int k = 0; k < 4; k++) {
            int ok = o + k;
            float bias = qkv_b[ok];
            #pragma unroll
            for (int ii = 0; ii < 4; ii++) {
                int t = tg * 4 + ii;
                float v = a[ii][k] + bias;
                if (ok < 96)       QT[ok * TP + t] = v;
                else if (ok < 192) KT[(ok - 96) * TP + t] = v;
                else               V[t * V_STR + (ok - 192)] = v;
            }
        }
    }
    __syncthreads();

    for (int idx = tid; idx < 507; idx += 256) {
        int h = idx / 169; int r = idx - h * 169;
        int ig = r / 13, jg = r - (r / 13) * 13;
        float a[4][4];
        #pragma unroll
        for (int ii = 0; ii < 4; ii++)
            #pragma unroll
            for (int jj = 0; jj < 4; jj++) a[ii][jj] = 0.0f;
        const float* qb = &QT[h * 32 * TP + ig * 4];
        const float* kb = &KT[h * 32 * TP + jg * 4];
        #pragma unroll 8
        for (int d = 0; d < 32; d++) {
            float4 qv = *reinterpret_cast<const float4*>(&qb[d * TP]);
            float4 kv = *reinterpret_cast<const float4*>(&kb[d * TP]);
            float qq[4] = {qv.x, qv.y, qv.z, qv.w};
            float kk[4] = {kv.x, kv.y, kv.z, kv.w};
            #pragma unroll
            for (int ii = 0; ii < 4; ii++)
                #pragma unroll
                for (int jj = 0; jj < 4; jj++) a[ii][jj] += qq[ii] * kk[jj];
        }
        #pragma unroll
        for (int ii = 0; ii < 4; ii++) {
            int i = ig * 4 + ii;
            if (i < TT) {
                #pragma unroll
                for (int jj = 0; jj < 4; jj++) {
                    int j = jg * 4 + jj;
                    if (j < TT)
                        S3[h * (TT * TT) + i * TT + j] = a[ii][jj] * 0.17677669529663687f;
                }
            }
        }
    }
    __syncthreads();

    for (int row = warp; row < 3 * TT; row += 8) {
        float* Sr = &S3[row * TT];
        float a0 = Sr[lane];
        float a1 = (lane < 17) ? Sr[32 + lane] : -1e30f;
        float mx = fmaxf(a0, a1);
        #pragma unroll
        for (int o = 16; o; o >>= 1) mx = fmaxf(mx, __shfl_xor_sync(~0u, mx, o));
        float e0 = __expf(a0 - mx);
        float e1 = (lane < 17) ? __expf(a1 - mx) : 0.0f;
        float ss = e0 + e1;
        #pragma unroll
        for (int o = 16; o; o >>= 1) ss += __shfl_xor_sync(~0u, ss, o);
        float inv = __fdividef(1.0f, ss);
        Sr[lane] = e0 * inv;
        if (lane < 17) Sr[32 + lane] = e1 * inv;
    }
    __syncthreads();

    for (int idx = tid; idx < 312; idx += 256) {
        int h = idx / 104; int r = idx - h * 104;
        int ig = r >> 3, dg = r & 7;
        float a[4][4];
        #pragma unroll
        for (int ii = 0; ii < 4; ii++)
            #pragma unroll
            for (int k = 0; k < 4; k++) a[ii][k] = 0.0f;
        const float* S0 = &S3[h * (TT * TT) + min(ig * 4 + 0, 48) * TT];
        const float* S1 = &S3[h * (TT * TT) + min(ig * 4 + 1, 48) * TT];
        const float* S2 = &S3[h * (TT * TT) + min(ig * 4 + 2, 48) * TT];
        const float* Sx = &S3[h * (TT * TT) + min(ig * 4 + 3, 48) * TT];
        const float* Vb = &V[h * 32 + dg * 4];
        #pragma unroll 7
        for (int j = 0; j < TT; j++) {
            float4 vv = *reinterpret_cast<const float4*>(&Vb[j * V_STR]);
            float vvv[4] = {vv.x, vv.y, vv.z, vv.w};
            float ss[4] = {S0[j], S1[j], S2[j], Sx[j]};
            #pragma unroll
            for (int ii = 0; ii < 4; ii++)
                #pragma unroll
                for (int k = 0; k < 4; k++) a[ii][k] += ss[ii] * vvv[k];
        }
        #pragma unroll
        for (int k = 0; k < 4; k++)
            #pragma unroll
            for (int ii = 0; ii < 4; ii++)
                AT[(h * 32 + dg * 4 + k) * TP + ig * 4 + ii] = a[ii][k];
    }
    __syncthreads();

    for (int idx = tid; idx < 312; idx += 256) {
        int tg = idx % 13, cg = idx / 13;
        int co = cg * 4;
        float a[4][4];
        #pragma unroll
        for (int ii = 0; ii < 4; ii++)
            #pragma unroll
            for (int k = 0; k < 4; k++) a[ii][k] = 0.0f;
        const float* atb = &AT[tg * 4];
        #pragma unroll 4
        for (int c = 0; c < CC; c++) {
            float4 ov = *reinterpret_cast<const float4*>(&atb[c * TP]);
            float4 wv = *reinterpret_cast<const float4*>(&d_projT[c * CC + co]);
            float oo[4] = {ov.x, ov.y, ov.z, ov.w};
            float ww[4] = {wv.x, wv.y, wv.z, wv.w};
            #pragma unroll
            for (int ii = 0; ii < 4; ii++)
                #pragma unroll
                for (int k = 0; k < 4; k++) a[ii][k] += oo[ii] * ww[k];
        }
        #pragma unroll
        for (int ii = 0; ii < 4; ii++) {
            int t = tg * 4 + ii;
            if (t < TT) {
                int ti = t / WS_, tj = t - ti * WS_;
                int dr = wi * WS_ + (ti + 3) % WS_;
                int dc = wj * WS_ + (tj + 3) % WS_;
                size_t off = ((size_t)(b * LL_ + dr * WW + dc)) * CC + co;
                float4 xr = *reinterpret_cast<const float4*>(&x[off]);
                float4 res = make_float4(xr.x + a[ii][0] + proj_b[co],
                                         xr.y + a[ii][1] + proj_b[co + 1],
                                         xr.z + a[ii][2] + proj_b[co + 2],
                                         xr.w + a[ii][3] + proj_b[co + 3]);
                *reinterpret_cast<float4*>(&d_x1[off]) = res;
            }
        }
    }
}

// ---------------------------------------------------------------------------
// Kernel 2: pin stage (packed uint4 stores — R6 fast path).
// ---------------------------------------------------------------------------
#define TB 16
#define PIN_SMEM (96 * TB * 4)

__global__ __launch_bounds__(128)
void pin_kernel(const float* __restrict__ n2g, const float* __restrict__ n2b,
                const float* __restrict__ nfg, const float* __restrict__ nfb,
                const float* __restrict__ pin_b) {
    extern __shared__ float smw[];
    float* WT = smw;                  // [96][16]

    const int tid  = threadIdx.x;
    const int lane = tid & 31;
    const int warp = tid >> 5;
    const int tg4  = (tid & 3) * 4;
    const size_t t0 = (size_t)blockIdx.x * TB;

    for (int tt = warp; tt < TB; tt += 4) {
        const float* row = d_x1 + (t0 + tt) * CC;
        float v0 = row[lane], v1 = row[lane + 32], v2 = row[lane + 64];
        float s = v0 + v1 + v2;
        #pragma unroll
        for (int o = 16; o; o >>= 1) s += __shfl_xor_sync(~0u, s, o);
        float m = s * (1.0f / 96.0f);
        float d0 = v0 - m, d1 = v1 - m, d2 = v2 - m;
        float vv = d0 * d0 + d1 * d1 + d2 * d2;
        #pragma unroll
        for (int o = 16; o; o >>= 1) vv += __shfl_xor_sync(~0u, vv, o);
        float inv = rsqrtf(vv * (1.0f / 96.0f) + 1e-5f);
        float z0 = d0 * inv * n2g[lane]      + n2b[lane];
        float z1 = d1 * inv * n2g[lane + 32] + n2b[lane + 32];
        float z2 = d2 * inv * n2g[lane + 64] + n2b[lane + 64];
        float s2 = z0 + z1 + z2;
        #pragma unroll
        for (int o = 16; o; o >>= 1) s2 += __shfl_xor_sync(~0u, s2, o);
        float m2 = s2 * (1.0f / 96.0f);
        float e0 = z0 - m2, e1 = z1 - m2, e2 = z2 - m2;
        float v2s = e0 * e0 + e1 * e1 + e2 * e2;
        #pragma unroll
        for (int o = 16; o; o >>= 1) v2s += __shfl_xor_sync(~0u, v2s, o);
        float inv2 = rsqrtf(v2s * (1.0f / 96.0f) + 1e-5f);
        WT[lane * TB + tt]        = e0 * inv2 * nfg[lane]      + nfb[lane];
        WT[(lane + 32) * TB + tt] = e1 * inv2 * nfg[lane + 32] + nfb[lane + 32];
        WT[(lane + 64) * TB + tt] = e2 * inv2 * nfg[lane + 64] + nfb[lane + 64];
    }
    __syncthreads();

    for (int hg = tid >> 2; hg < HID_ / 4; hg += 32) {
        int h = hg * 4;
        float a[4][4];
        #pragma unroll
        for (int ii = 0; ii < 4; ii++)
            #pragma unroll
            for (int k = 0; k < 4; k++) a[ii][k] = 0.0f;
        #pragma unroll 8
        for (int c = 0; c < CC; c++) {
            float4 wv = *reinterpret_cast<const float4*>(&WT[c * TB + tg4]);
            float4 p  = *reinterpret_cast<const float4*>(&d_pinT[c * HID_ + h]);
            float ww[4] = {wv.x, wv.y, wv.z, wv.w};
            float pp[4] = {p.x, p.y, p.z, p.w};
            #pragma unroll
            for (int ii = 0; ii < 4; ii++)
                #pragma unroll
                for (int k = 0; k < 4; k++) a[ii][k] += ww[ii] * pp[k];
        }
        float bias[4] = {pin_b[h], pin_b[h + 1], pin_b[h + 2], pin_b[h + 3]};
        #pragma unroll
        for (int ii = 0; ii < 4; ii++) {
            unsigned u1[4], u2[4];
            #pragma unroll
            for (int k = 0; k < 4; k++) {
                float v = a[ii][k] + bias[k];
                // log(sig(v)) = -softplus(-v);  log(1-sig(v)) = -softplus(v)
                float spn = (v < -15.f) ? -v : __logf(1.0f + __expf(-v));
                float spp = (v >  15.f) ?  v : __logf(1.0f + __expf(v));
                u1[k] = pack_ll(fmaxf(-spn, LOG_EPS));
                u2[k] = pack_ll(fmaxf(-spp, LOG_EPS));
            }
            size_t t = t0 + tg4 + ii;
            *reinterpret_cast<uint4*>(&d_ll[t * TWOH + h]) =
                make_uint4(u1[0], u1[1], u1[2], u1[3]);
            *reinterpret_cast<uint4*>(&d_ll[t * TWOH + HID_ + h]) =
                make_uint4(u2[0], u2[1], u2[2], u2[3]);
        }
    }
}

// ---------------------------------------------------------------------------
// Kernel 3: clause GEMM, 64 tokens / CTA (784 CTAs), 256 threads (8 warps).
// Warp w: tokens [(w>>1)*16, +16) x clauses [(w&1)*64, +64) -> 32 acc regs.
// Register-prefetch double buffering, split-on-STS from packed d_ll,
// ldmatrix A frags, mask B frags via LDG.128 from pre-fragmented gmem.
// ---------------------------------------------------------------------------
#define NTOK 64
#define BUF_SZ 18432                        // hi(9216) + lo(9216) per buffer
#define CLT_STR 68
#define CLA_SMEM (2 * BUF_SZ)               // 36864; CLT (34816) overlays

__global__ __launch_bounds__(256)
void clause_kernel(const float* __restrict__ tm_out,
                   const float* __restrict__ gate,
                   float* __restrict__ out) {
    extern __shared__ char smc[];
    const uint32_t sb = smem_u32(smc);
    float* CLT = reinterpret_cast<float*>(smc);

    const int tid  = threadIdx.x;
    const int wid  = tid >> 5;
    const int lane = tid & 31;
    const int qr   = lane >> 2;
    const int qc   = (lane & 3) * 2;
    const int t0   = blockIdx.x * NTOK;
    const int r0   = (wid >> 1) * 16;       // token rows
    const int ch2  = wid & 1;               // clause half (64 clauses)

    float acc[32];
    #pragma unroll
    for (int i = 0; i < 32; i++) acc[i] = 0.0f;

    // staging indices: idx = tid + i*256; row = idx>>4 (token), col = idx&15 (4 k each)
    const int srow = tid >> 4;
    const int scol = tid & 15;
    const unsigned* __restrict__ llbase =
        d_ll + (size_t)(t0 + srow) * TWOH + scol * 4;
    const uint32_t sdst = srow * 144 + scol * 8;

    // prologue: load + stage chunk 0 into buffer 0
    uint4 pf[4];
    #pragma unroll
    for (int i = 0; i < 4; i++)
        pf[i] = *reinterpret_cast<const uint4*>(llbase + (size_t)(i * 16) * TWOH);
    #pragma unroll
    for (int i = 0; i < 4; i++) {
        uint4 p = pf[i];
        uint32_t h01 = (p.x & 0xffffu) | (p.y << 16);
        uint32_t h23 = (p.z & 0xffffu) | (p.w << 16);
        uint32_t l01 = (p.x >> 16) | (p.y & 0xffff0000u);
        uint32_t l23 = (p.z >> 16) | (p.w & 0xffff0000u);
        uint32_t d = sdst + i * 16 * 144;
        *reinterpret_cast<uint2*>(smc + d)        = make_uint2(h01, h23);
        *reinterpret_cast<uint2*>(smc + d + 9216) = make_uint2(l01, l23);
    }
    __syncthreads();

    const uint32_t arow = r0 + (lane & 15);
    for (int ch = 0; ch < 12; ch++) {
        // prefetch next chunk into registers (overlaps MMA below)
        if (ch < 11) {
            #pragma unroll
            for (int i = 0; i < 4; i++)
                pf[i] = *reinterpret_cast<const uint4*>(
                    llbase + (ch + 1) * 64 + (size_t)(i * 16) * TWOH);
        }

        const uint32_t bufb = sb + (ch & 1) * BUF_SZ;
        const uint32_t abase = bufb + arow * 144 + ((lane >> 4) * 8) * 2;
        #pragma unroll
        for (int ks = 0; ks < 4; ks++) {
            uint32_t ah[4], al[4];
            uint32_t addr = abase + ks * 32;
            LDMX4(ah, addr);
            LDMX4(al, addr + 9216);
            const uint4* __restrict__ mf =
                d_maskF + ((ch * 4 + ks) * 8 + ch2 * 4) * 32 + lane;
            #pragma unroll
            for (int ntp = 0; ntp < 4; ntp++) {
                uint4 b = mf[ntp * 32];
                mma16816(&acc[(2 * ntp) * 4],     ah[0], ah[1], ah[2], ah[3], b.x, b.y);
                mma16816(&acc[(2 * ntp) * 4],     al[0], al[1], al[2], al[3], b.x, b.y);
                mma16816(&acc[(2 * ntp + 1) * 4], ah[0], ah[1], ah[2], ah[3], b.z, b.w);
                mma16816(&acc[(2 * ntp + 1) * 4], al[0], al[1], al[2], al[3], b.z, b.w);
            }
        }

        if (ch < 11) {
            // stage next chunk into the other buffer (no sync needed before:
            // it writes the buffer whose MMA reads finished last iteration)
            const uint32_t nb = sb + ((ch + 1) & 1) * BUF_SZ;
            (void)nb;
            char* dstb = smc + ((ch + 1) & 1) * BUF_SZ;
            #pragma unroll
            for (int i = 0; i < 4; i++) {
                uint4 p = pf[i];
                uint32_t h01 = (p.x & 0xffffu) | (p.y << 16);
                uint32_t h23 = (p.z & 0xffffu) | (p.w << 16);
                uint32_t l01 = (p.x >> 16) | (p.y & 0xffff0000u);
                uint32_t l23 = (p.z >> 16) | (p.w & 0xffff0000u);
                uint32_t d = sdst + i * 16 * 144;
                *reinterpret_cast<uint2*>(dstb + d)        = make_uint2(h01, h23);
                *reinterpret_cast<uint2*>(dstb + d + 9216) = make_uint2(l01, l23);
            }
            __syncthreads();
        }
    }
    __syncthreads();   // staging buffers dead; CLT overlays

    // exp + transposed store: CLT[j][t_local]
    #pragma unroll
    for (int nt = 0; nt < 8; nt++) {
        int j = ch2 * 64 + nt * 8 + qc;
        CLT[j * CLT_STR + r0 + qr]           = __expf(acc[nt * 4 + 0]);
        CLT[(j + 1) * CLT_STR + r0 + qr]     = __expf(acc[nt * 4 + 1]);
        CLT[j * CLT_STR + r0 + qr + 8]       = __expf(acc[nt * 4 + 2]);
        CLT[(j + 1) * CLT_STR + r0 + qr + 8] = __expf(acc[nt * 4 + 3]);
    }
    __syncthreads();

    // logits = clauses @ tm_out; gated blend + residual
    const float g = __fdividef(1.0f, 1.0f + __expf(-gate[0]));
    for (int idx = tid; idx < 16 * 24; idx += 256) {
        int tg = idx & 15, cg = idx >> 4;
        float a[4][4];
        #pragma unroll
        for (int ii = 0; ii < 4; ii++)
            #pragma unroll
            for (int k = 0; k < 4; k++) a[ii][k] = 0.0f;
        const float* clb = &CLT[tg * 4];
        const float* ob  = &tm_out[cg * 4];
        #pragma unroll 8
        for (int j = 0; j < NCL_; j++) {
            float4 cv = *reinterpret_cast<const float4*>(&clb[j * CLT_STR]);
            float4 ov = *reinterpret_cast<const float4*>(&ob[j * CC]);
            float cc[4] = {cv.x, cv.y, cv.z, cv.w};
            float oo[4] = {ov.x, ov.y, ov.z, ov.w};
            #pragma unroll
            for (int ii = 0; ii < 4; ii++)
                #pragma unroll
                for (int k = 0; k < 4; k++) a[ii][k] += cc[ii] * oo[k];
        }
        #pragma unroll
        for (int ii = 0; ii < 4; ii++) {
            size_t off = (size_t)(t0 + tg * 4 + ii) * CC + cg * 4;
            float4 xr = *reinterpret_cast<const float4*>(&d_x1[off]);
            float r[4];
            #pragma unroll
            for (int k = 0; k < 4; k++) {
                float lg = a[ii][k];
                float sg = __fdividef(1.0f, 1.0f + __expf(-lg));
                r[k] = g * lg + (1.0f - g) * sg;
            }
            float4 res = make_float4(xr.x + r[0], xr.y + r[1], xr.z + r[2], xr.w + r[3]);
            *reinterpret_cast<float4*>(&out[off]) = res;
        }
    }
}

// ---------------------------------------------------------------------------
extern "C" void kernel_launch(void* const* d_in, const int* in_sizes, int n_in,
                              void* d_out, int out_size) {
    (void)in_sizes; (void)n_in; (void)out_size;
    const float* x      = (const float*)d_in[0];
    const float* n1g    = (const float*)d_in[1];
    const float* n1b    = (const float*)d_in[2];
    const float* qkv_w  = (const float*)d_in[3];
    const float* qkv_b  = (const float*)d_in[4];
    const float* proj_w = (const float*)d_in[5];
    const float* proj_b = (const float*)d_in[6];
    const float* n2g    = (const float*)d_in[7];
    const float* n2b    = (const float*)d_in[8];
    const float* nfg    = (const float*)d_in[9];
    const float* nfb    = (const float*)d_in[10];
    const float* pin_w  = (const float*)d_in[11];
    const float* pin_b  = (const float*)d_in[12];
    const float* tm_inc = (const float*)d_in[13];
    const float* tm_out = (const float*)d_in[14];
    const float* gate   = (const float*)d_in[15];
    float* out = (float*)d_out;

    cudaFuncSetAttribute(attn_kernel,   cudaFuncAttributeMaxDynamicSharedMemorySize, ATTN_SMEM);
    cudaFuncSetAttribute(clause_kernel, cudaFuncAttributeMaxDynamicSharedMemorySize, CLA_SMEM);

    prep_kernel<<<336, 256>>>(tm_inc, pin_w, qkv_w, proj_w);
    attn_kernel<<<BB * 64, 256, ATTN_SMEM>>>(x, n1g, n1b, qkv_b, proj_b);
    pin_kernel<<<NTOT / TB, 128, PIN_SMEM>>>(n2g, n2b, nfg, nfb, pin_b);
    clause_kernel<<<NTOT / NTOK, 256, CLA_SMEM>>>(tm_out, gate, out);
}

// round 13
// speedup vs baseline: 1.1315x; 1.0865x over previous
#include <cuda_runtime.h>
#include <cuda_bf16.h>
#include <math.h>
#include <stdint.h>

// Problem constants
#define BB   16
#define HH   56
#define WW   56
#define CC   96
#define LL_  3136        // 56*56
#define NHD  3
#define WS_  7
#define TT   49
#define HID_ 384
#define NCL_ 128
#define TWOH 768
#define NTOT (BB * LL_)  // 50176 tokens

#define LOG_EPS -13.815511f   // log(1e-6)

// ---------------------------------------------------------------------------
// device-global scratch (no allocation allowed)
// ---------------------------------------------------------------------------
__device__ float d_x1[NTOT * CC];                  // residual after attention
__device__ uint4 d_maskF[12 * 4 * 8 * 32];         // pre-fragmented mask B operands
__device__ float d_pinT[CC * HID_];                // pin_w^T [c][h]
__device__ float d_qkvT[CC * 288];                 // qkv_w^T [c][o]
__device__ float d_projT[CC * CC];                 // proj_w^T [c][o]

// ---------------------------------------------------------------------------
// helpers
// ---------------------------------------------------------------------------
__device__ __forceinline__ uint32_t smem_u32(const void* p) {
    uint32_t a;
    asm("{ .reg .u64 t; cvta.to.shared.u64 t, %1; cvt.u32.u64 %0, t; }" : "=r"(a) : "l"(p));
    return a;
}

#define LDMX4(r, a) \
    asm volatile("ldmatrix.sync.aligned.m8n8.x4.shared.b16 {%0,%1,%2,%3}, [%4];" \
                 : "=r"((r)[0]), "=r"((r)[1]), "=r"((r)[2]), "=r"((r)[3]) : "r"(a))

__device__ __forceinline__ void mma16816(float* d, uint32_t a0, uint32_t a1,
                                         uint32_t a2, uint32_t a3,
                                         uint32_t b0, uint32_t b1) {
    asm volatile(
        "mma.sync.aligned.m16n8k16.row.col.f32.bf16.bf16.f32 "
        "{%0,%1,%2,%3}, {%4,%5,%6,%7}, {%8,%9}, {%0,%1,%2,%3};"
        : "+f"(d[0]), "+f"(d[1]), "+f"(d[2]), "+f"(d[3])
        : "r"(a0), "r"(a1), "r"(a2), "r"(a3), "r"(b0), "r"(b1));
}

__device__ __forceinline__ unsigned bmask_bits(float v) {
    return v > 0.0f ? 0x3F80u : 0u;   // bf16 1.0 / 0.0
}

__device__ __forceinline__ unsigned short bfh(float f) {
    return __bfloat16_as_ushort(__float2bfloat16(f));
}

// ---------------------------------------------------------------------------
// Prep: pre-fragment binarized mask for mma B operands; transpose weights.
// ---------------------------------------------------------------------------
__global__ void prep_kernel(const float* __restrict__ tm_inc,
                            const float* __restrict__ pin_w,
                            const float* __restrict__ qkv_w,
                            const float* __restrict__ proj_w) {
    int i = blockIdx.x * 256 + threadIdx.x;
    if (i < 12288) {
        int lane = i & 31, ntp = (i >> 5) & 7, ks = (i >> 8) & 3, ch = i >> 10;
        int qr = lane >> 2;
        int k  = ch * 64 + ks * 16 + (lane & 3) * 2;
        int n0 = ntp * 16 + qr, n1 = n0 + 8;
        const float* p0 = tm_inc + n0 * TWOH;
        const float* p1 = tm_inc + n1 * TWOH;
        uint4 u;
        u.x = bmask_bits(p0[k])     | (bmask_bits(p0[k + 1]) << 16);
        u.y = bmask_bits(p0[k + 8]) | (bmask_bits(p0[k + 9]) << 16);
        u.z = bmask_bits(p1[k])     | (bmask_bits(p1[k + 1]) << 16);
        u.w = bmask_bits(p1[k + 8]) | (bmask_bits(p1[k + 9]) << 16);
        d_maskF[i] = u;
        return;
    }
    i -= 12288;
    if (i < HID_ * CC) {
        int h = i / CC, c = i - h * CC;
        d_pinT[c * HID_ + h] = pin_w[i];
        return;
    }
    i -= HID_ * CC;
    if (i < 288 * CC) {
        int o = i / CC, c = i - o * CC;
        d_qkvT[c * 288 + o] = qkv_w[i];
        return;
    }
    i -= 288 * CC;
    if (i < CC * CC) {
        int o = i / CC, c = i - o * CC;
        d_projT[c * CC + o] = proj_w[i];
    }
}

// ---------------------------------------------------------------------------
// Kernel 1: fused window attention (unchanged — 4x4 register tiles)
// ---------------------------------------------------------------------------
#define TP 52
#define AT_SZ  (96 * TP)
#define QT_SZ  (96 * TP)
#define KT_SZ  (96 * TP)
#define V_STR  100
#define V_SZ   (TP * V_STR)
#define S3_SZ  (3 * 49 * 49)
#define ATTN_SMEM ((AT_SZ + QT_SZ + KT_SZ + V_SZ + S3_SZ) * 4)

__global__ __launch_bounds__(256)
void attn_kernel(const float* __restrict__ x,
                 const float* __restrict__ n1g, const float* __restrict__ n1b,
                 const float* __restrict__ qkv_b,
                 const float* __restrict__ proj_b) {
    extern __shared__ float sm[];
    float* AT = sm;
    float* QT = AT + AT_SZ;
    float* KT = QT + QT_SZ;
    float* V  = KT + KT_SZ;
    float* S3 = V + V_SZ;

    const int tid  = threadIdx.x;
    const int lane = tid & 31;
    const int warp = tid >> 5;
    const int bw = blockIdx.x;
    const int b  = bw >> 6;
    const int wi = (bw >> 3) & 7;
    const int wj = bw & 7;

    for (int t = warp; t < TT; t += 8) {
        int ti = t / WS_, tj = t - ti * WS_;
        int r = (wi * WS_ + ti + 3) % HH;
        int c = (wj * WS_ + tj + 3) % WW;
        const float* row = x + ((size_t)(b * LL_ + r * WW + c)) * CC;
        float v0 = row[lane], v1 = row[lane + 32], v2 = row[lane + 64];
        float s = v0 + v1 + v2;
        #pragma unroll
        for (int o = 16; o; o >>= 1) s += __shfl_xor_sync(~0u, s, o);
        float m = s * (1.0f / 96.0f);
        float d0 = v0 - m, d1 = v1 - m, d2 = v2 - m;
        float vv = d0 * d0 + d1 * d1 + d2 * d2;
        #pragma unroll
        for (int o = 16; o; o >>= 1) vv += __shfl_xor_sync(~0u, vv, o);
        float inv = rsqrtf(vv * (1.0f / 96.0f) + 1e-5f);
        AT[lane * TP + t]        = d0 * inv * n1g[lane]      + n1b[lane];
        AT[(lane + 32) * TP + t] = d1 * inv * n1g[lane + 32] + n1b[lane + 32];
        AT[(lane + 64) * TP + t] = d2 * inv * n1g[lane + 64] + n1b[lane + 64];
    }
    __syncthreads();

    for (int idx = tid; idx < 13 * 72; idx += 256) {
        int og = idx % 72, tg = idx / 72;
        int o = og * 4;
        float a[4][4];
        #pragma unroll
        for (int ii = 0; ii < 4; ii++)
            #pragma unroll
            for (int k = 0; k < 4; k++) a[ii][k] = 0.0f;
        const float* atb = &AT[tg * 4];
        #pragma unroll 4
        for (int c = 0; c < CC; c++) {
            float4 av = *reinterpret_cast<const float4*>(&atb[c * TP]);
            float4 wv = *reinterpret_cast<const float4*>(&d_qkvT[c * 288 + o]);
            float avv[4] = {av.x, av.y, av.z, av.w};
            float wvv[4] = {wv.x, wv.y, wv.z, wv.w};
            #pragma unroll
            for (int ii = 0; ii < 4; ii++)
                #pragma unroll
                for (int k = 0; k < 4; k++) a[ii][k] += avv[ii] * wvv[k];
        }
        #pragma unroll
        for (int k = 0; k < 4; k++) {
            int ok = o + k;
            float bias = qkv_b[ok];
            #pragma unroll
            for (int ii = 0; ii < 4; ii++) {
                int t = tg * 4 + ii;
                float v = a[ii][k] + bias;
                if (ok < 96)       QT[ok * TP + t] = v;
                else if (ok < 192) KT[(ok - 96) * TP + t] = v;
                else               V[t * V_STR + (ok - 192)] = v;
            }
        }
    }
    __syncthreads();

    for (int idx = tid; idx < 507; idx += 256) {
        int h = idx / 169; int r = idx - h * 169;
        int ig = r / 13, jg = r - (r / 13) * 13;
        float a[4][4];
        #pragma unroll
        for (int ii = 0; ii < 4; ii++)
            #pragma unroll
            for (int jj = 0; jj < 4; jj++) a[ii][jj] = 0.0f;
        const float* qb = &QT[h * 32 * TP + ig * 4];
        const float* kb = &KT[h * 32 * TP + jg * 4];
        #pragma unroll 8
        for (int d = 0; d < 32; d++) {
            float4 qv = *reinterpret_cast<const float4*>(&qb[d * TP]);
            float4 kv = *reinterpret_cast<const float4*>(&kb[d * TP]);
            float qq[4] = {qv.x, qv.y, qv.z, qv.w};
            float kk[4] = {kv.x, kv.y, kv.z, kv.w};
            #pragma unroll
            for (int ii = 0; ii < 4; ii++)
                #pragma unroll
                for (int jj = 0; jj < 4; jj++) a[ii][jj] += qq[ii] * kk[jj];
        }
        #pragma unroll
        for (int ii = 0; ii < 4; ii++) {
            int i = ig * 4 + ii;
            if (i < TT) {
                #pragma unroll
                for (int jj = 0; jj < 4; jj++) {
                    int j = jg * 4 + jj;
                    if (j < TT)
                        S3[h * (TT * TT) + i * TT + j] = a[ii][jj] * 0.17677669529663687f;
                }
            }
        }
    }
    __syncthreads();

    for (int row = warp; row < 3 * TT; row += 8) {
        float* Sr = &S3[row * TT];
        float a0 = Sr[lane];
        float a1 = (lane < 17) ? Sr[32 + lane] : -1e30f;
        float mx = fmaxf(a0, a1);
        #pragma unroll
        for (int o = 16; o; o >>= 1) mx = fmaxf(mx, __shfl_xor_sync(~0u, mx, o));
        float e0 = __expf(a0 - mx);
        float e1 = (lane < 17) ? __expf(a1 - mx) : 0.0f;
        float ss = e0 + e1;
        #pragma unroll
        for (int o = 16; o; o >>= 1) ss += __shfl_xor_sync(~0u, ss, o);
        float inv = __fdividef(1.0f, ss);
        Sr[lane] = e0 * inv;
        if (lane < 17) Sr[32 + lane] = e1 * inv;
    }
    __syncthreads();

    for (int idx = tid; idx < 312; idx += 256) {
        int h = idx / 104; int r = idx - h * 104;
        int ig = r >> 3, dg = r & 7;
        float a[4][4];
        #pragma unroll
        for (int ii = 0; ii < 4; ii++)
            #pragma unroll
            for (int k = 0; k < 4; k++) a[ii][k] = 0.0f;
        const float* S0 = &S3[h * (TT * TT) + min(ig * 4 + 0, 48) * TT];
        const float* S1 = &S3[h * (TT * TT) + min(ig * 4 + 1, 48) * TT];
        const float* S2 = &S3[h * (TT * TT) + min(ig * 4 + 2, 48) * TT];
        const float* Sx = &S3[h * (TT * TT) + min(ig * 4 + 3, 48) * TT];
        const float* Vb = &V[h * 32 + dg * 4];
        #pragma unroll 7
        for (int j = 0; j < TT; j++) {
            float4 vv = *reinterpret_cast<const float4*>(&Vb[j * V_STR]);
            float vvv[4] = {vv.x, vv.y, vv.z, vv.w};
            float ss[4] = {S0[j], S1[j], S2[j], Sx[j]};
            #pragma unroll
            for (int ii = 0; ii < 4; ii++)
                #pragma unroll
                for (int k = 0; k < 4; k++) a[ii][k] += ss[ii] * vvv[k];
        }
        #pragma unroll
        for (int k = 0; k < 4; k++)
            #pragma unroll
            for (int ii = 0; ii < 4; ii++)
                AT[(h * 32 + dg * 4 + k) * TP + ig * 4 + ii] = a[ii][k];
    }
    __syncthreads();

    for (int idx = tid; idx < 312; idx += 256) {
        int tg = idx % 13, cg = idx / 13;
        int co = cg * 4;
        float a[4][4];
        #pragma unroll
        for (int ii = 0; ii < 4; ii++)
            #pragma unroll
            for (int k = 0; k < 4; k++) a[ii][k] = 0.0f;
        const float* atb = &AT[tg * 4];
        #pragma unroll 4
        for (int c = 0; c < CC; c++) {
            float4 ov = *reinterpret_cast<const float4*>(&atb[c * TP]);
            float4 wv = *reinterpret_cast<const float4*>(&d_projT[c * CC + co]);
            float oo[4] = {ov.x, ov.y, ov.z, ov.w};
            float ww[4] = {wv.x, wv.y, wv.z, wv.w};
            #pragma unroll
            for (int ii = 0; ii < 4; ii++)
                #pragma unroll
                for (int k = 0; k < 4; k++) a[ii][k] += oo[ii] * ww[k];
        }
        #pragma unroll
        for (int ii = 0; ii < 4; ii++) {
            int t = tg * 4 + ii;
            if (t < TT) {
                int ti = t / WS_, tj = t - ti * WS_;
                int dr = wi * WS_ + (ti + 3) % WS_;
                int dc = wj * WS_ + (tj + 3) % WS_;
                size_t off = ((size_t)(b * LL_ + dr * WW + dc)) * CC + co;
                float4 xr = *reinterpret_cast<const float4*>(&x[off]);
                float4 res = make_float4(xr.x + a[ii][0] + proj_b[co],
                                         xr.y + a[ii][1] + proj_b[co + 1],
                                         xr.z + a[ii][2] + proj_b[co + 2],
                                         xr.w + a[ii][3] + proj_b[co + 3]);
                *reinterpret_cast<float4*>(&d_x1[off]) = res;
            }
        }
    }
}

// ---------------------------------------------------------------------------
// Kernel 2: FUSED TM-FFN. 64 tokens / CTA (784 CTAs), 256 threads (8 warps).
// LN2+LNffn -> WT smem. Then per 64-hidden chunk hc (6 chunks):
//   pin GEMM (fp32, 4tok x 4hid register tiles) -> softplus loglits (1 exp +
//   1 log via softplus(v)=log1p(e^-|v|)+max(v,0)) -> hi/lo bf16 smem staging
//   -> clause mma.sync for K-chunks hc (pos lits) and hc+6 (neg lits).
// Epilogue: exp -> CLT[j][t] -> fp32 tm_out GEMM -> gated blend + residual.
// No gmem loglit round-trip.
// ---------------------------------------------------------------------------
#define NTOK 64
#define WT_STR 68
#define WT_SZ  (96 * WT_STR * 4)            // 26112 B
#define LLOFF  WT_SZ
#define LL_ROW 144                          // 64 bf16 + 16B pad
#define LLB    (64 * LL_ROW)                // 9216 B per buffer
#define CLT_STR 68
#define FFN_SMEM (WT_SZ + 4 * LLB)          // 62976 B; CLT (34816) overlays

__global__ __launch_bounds__(256)
void ffn_kernel(const float* __restrict__ n2g, const float* __restrict__ n2b,
                const float* __restrict__ nfg, const float* __restrict__ nfb,
                const float* __restrict__ pin_b,
                const float* __restrict__ tm_out,
                const float* __restrict__ gate,
                float* __restrict__ out) {
    extern __shared__ char smc[];
    const uint32_t sb = smem_u32(smc);
    float* WT  = reinterpret_cast<float*>(smc);
    float* CLT = reinterpret_cast<float*>(smc);

    const int tid  = threadIdx.x;
    const int wid  = tid >> 5;
    const int lane = tid & 31;
    const int qr   = lane >> 2;
    const int qc   = (lane & 3) * 2;
    const int t0   = blockIdx.x * NTOK;
    const int r0   = (wid >> 1) * 16;       // MMA token rows
    const int ch2  = wid & 1;               // MMA clause half

    // pin-GEMM thread mapping: hgrp fast (coalesced pinT loads, 2-way STS)
    const int tgrp = tid >> 4;              // 0..15
    const int hgrp = tid & 15;              // 0..15
    const int tg4  = tgrp * 4;
    const int h4   = hgrp * 4;

    // --- 1. LN2 then LN_ffn -> WT[c][t], stride 68 ---
    for (int tt = wid; tt < NTOK; tt += 8) {
        const float* row = d_x1 + (size_t)(t0 + tt) * CC;
        float v0 = row[lane], v1 = row[lane + 32], v2 = row[lane + 64];
        float s = v0 + v1 + v2;
        #pragma unroll
        for (int o = 16; o; o >>= 1) s += __shfl_xor_sync(~0u, s, o);
        float m = s * (1.0f / 96.0f);
        float d0 = v0 - m, d1 = v1 - m, d2 = v2 - m;
        float vv = d0 * d0 + d1 * d1 + d2 * d2;
        #pragma unroll
        for (int o = 16; o; o >>= 1) vv += __shfl_xor_sync(~0u, vv, o);
        float inv = rsqrtf(vv * (1.0f / 96.0f) + 1e-5f);
        float z0 = d0 * inv * n2g[lane]      + n2b[lane];
        float z1 = d1 * inv * n2g[lane + 32] + n2b[lane + 32];
        float z2 = d2 * inv * n2g[lane + 64] + n2b[lane + 64];
        float s2 = z0 + z1 + z2;
        #pragma unroll
        for (int o = 16; o; o >>= 1) s2 += __shfl_xor_sync(~0u, s2, o);
        float m2 = s2 * (1.0f / 96.0f);
        float e0 = z0 - m2, e1 = z1 - m2, e2 = z2 - m2;
        float v2s = e0 * e0 + e1 * e1 + e2 * e2;
        #pragma unroll
        for (int o = 16; o; o >>= 1) v2s += __shfl_xor_sync(~0u, v2s, o);
        float inv2 = rsqrtf(v2s * (1.0f / 96.0f) + 1e-5f);
        WT[lane * WT_STR + tt]        = e0 * inv2 * nfg[lane]      + nfb[lane];
        WT[(lane + 32) * WT_STR + tt] = e1 * inv2 * nfg[lane + 32] + nfb[lane + 32];
        WT[(lane + 64) * WT_STR + tt] = e2 * inv2 * nfg[lane + 64] + nfb[lane + 64];
    }
    __syncthreads();

    float acc[32];
    #pragma unroll
    for (int i = 0; i < 32; i++) acc[i] = 0.0f;

    const uint32_t arow_off = (r0 + (lane & 15)) * LL_ROW + ((lane >> 4) * 8) * 2;

    #pragma unroll 1
    for (int hc = 0; hc < 6; hc++) {
        // --- 2a. pin GEMM: 4 tokens x 4 hidden per thread ---
        float a[4][4];
        #pragma unroll
        for (int ii = 0; ii < 4; ii++)
            #pragma unroll
            for (int k = 0; k < 4; k++) a[ii][k] = 0.0f;
        const float* pw = d_pinT + hc * 64 + h4;
        #pragma unroll 8
        for (int c = 0; c < CC; c++) {
            float4 wv = *reinterpret_cast<const float4*>(&WT[c * WT_STR + tg4]);
            float4 p  = *reinterpret_cast<const float4*>(&pw[c * HID_]);
            float ww[4] = {wv.x, wv.y, wv.z, wv.w};
            float pp[4] = {p.x, p.y, p.z, p.w};
            #pragma unroll
            for (int ii = 0; ii < 4; ii++)
                #pragma unroll
                for (int k = 0; k < 4; k++) a[ii][k] += ww[ii] * pp[k];
        }
        const int hb = hc * 64 + h4;
        float bias[4] = {pin_b[hb], pin_b[hb + 1], pin_b[hb + 2], pin_b[hb + 3]};

        // --- 2b. softplus loglits -> hi/lo bf16 staging ---
        #pragma unroll
        for (int ii = 0; ii < 4; ii++) {
            unsigned ph[2], pl[2], nh[2], nl[2];
            #pragma unroll
            for (int k = 0; k < 4; k++) {
                float v = a[ii][k] + bias[k];
                float u = __logf(1.0f + __expf(-fabsf(v)));
                float lp = fmaxf(-(u + fmaxf(-v, 0.0f)), LOG_EPS); // log(sig)
                float ln = fmaxf(-(u + fmaxf( v, 0.0f)), LOG_EPS); // log(1-sig)
                unsigned short lph = bfh(lp);
                unsigned short lnh = bfh(ln);
                unsigned short lpl = bfh(lp - __bfloat162float(__ushort_as_bfloat16(lph)));
                unsigned short lnl = bfh(ln - __bfloat162float(__ushort_as_bfloat16(lnh)));
                ph[k >> 1] = (k & 1) ? (ph[k >> 1] | ((unsigned)lph << 16)) : lph;
                pl[k >> 1] = (k & 1) ? (pl[k >> 1] | ((unsigned)lpl << 16)) : lpl;
                nh[k >> 1] = (k & 1) ? (nh[k >> 1] | ((unsigned)lnh << 16)) : lnh;
                nl[k >> 1] = (k & 1) ? (nl[k >> 1] | ((unsigned)lnl << 16)) : lnl;
            }
            char* dst = smc + LLOFF + (tg4 + ii) * LL_ROW + h4 * 2;
            *reinterpret_cast<uint2*>(dst)            = make_uint2(ph[0], ph[1]);
            *reinterpret_cast<uint2*>(dst + LLB)      = make_uint2(pl[0], pl[1]);
            *reinterpret_cast<uint2*>(dst + 2 * LLB)  = make_uint2(nh[0], nh[1]);
            *reinterpret_cast<uint2*>(dst + 3 * LLB)  = make_uint2(nl[0], nl[1]);
        }
        __syncthreads();

        // --- 2c. clause MMA for K-chunks hc (pos) and hc+6 (neg) ---
        #pragma unroll
        for (int part = 0; part < 2; part++) {
            const uint32_t hibase = sb + LLOFF + part * 2 * LLB + arow_off;
            const int ch = hc + part * 6;
            #pragma unroll
            for (int ks = 0; ks < 4; ks++) {
                uint32_t ah[4], al[4];
                uint32_t addr = hibase + ks * 32;
                LDMX4(ah, addr);
                LDMX4(al, addr + LLB);
                const uint4* __restrict__ mf =
                    d_maskF + ((ch * 4 + ks) * 8 + ch2 * 4) * 32 + lane;
                #pragma unroll
                for (int ntp = 0; ntp < 4; ntp++) {
                    uint4 b = mf[ntp * 32];
                    mma16816(&acc[(2 * ntp) * 4],     ah[0], ah[1], ah[2], ah[3], b.x, b.y);
                    mma16816(&acc[(2 * ntp) * 4],     al[0], al[1], al[2], al[3], b.x, b.y);
                    mma16816(&acc[(2 * ntp + 1) * 4], ah[0], ah[1], ah[2], ah[3], b.z, b.w);
                    mma16816(&acc[(2 * ntp + 1) * 4], al[0], al[1], al[2], al[3], b.z, b.w);
                }
            }
        }
        __syncthreads();
    }

    // --- 3. exp + transposed store: CLT[j][t_local] (overlays WT/LL) ---
    #pragma unroll
    for (int nt = 0; nt < 8; nt++) {
        int j = ch2 * 64 + nt * 8 + qc;
        CLT[j * CLT_STR + r0 + qr]           = __expf(acc[nt * 4 + 0]);
        CLT[(j + 1) * CLT_STR + r0 + qr]     = __expf(acc[nt * 4 + 1]);
        CLT[j * CLT_STR + r0 + qr + 8]       = __expf(acc[nt * 4 + 2]);
        CLT[(j + 1) * CLT_STR + r0 + qr + 8] = __expf(acc[nt * 4 + 3]);
    }
    __syncthreads();

    // --- 4. logits = clauses @ tm_out; gated blend + residual ---
    const float g = __fdividef(1.0f, 1.0f + __expf(-gate[0]));
    for (int idx = tid; idx < 16 * 24; idx += 256) {
        int tg = idx & 15, cg = idx >> 4;
        float a[4][4];
        #pragma unroll
        for (int ii = 0; ii < 4; ii++)
            #pragma unroll
            for (int k = 0; k < 4; k++) a[ii][k] = 0.0f;
        const float* clb = &CLT[tg * 4];
        const float* ob  = &tm_out[cg * 4];
        #pragma unroll 8
        for (int j = 0; j < NCL_; j++) {
            float4 cv = *reinterpret_cast<const float4*>(&clb[j * CLT_STR]);
            float4 ov = *reinterpret_cast<const float4*>(&ob[j * CC]);
            float cc[4] = {cv.x, cv.y, cv.z, cv.w};
            float oo[4] = {ov.x, ov.y, ov.z, ov.w};
            #pragma unroll
            for (int ii = 0; ii < 4; ii++)
                #pragma unroll
                for (int k = 0; k < 4; k++) a[ii][k] += cc[ii] * oo[k];
        }
        #pragma unroll
        for (int ii = 0; ii < 4; ii++) {
            size_t off = (size_t)(t0 + tg * 4 + ii) * CC + cg * 4;
            float4 xr = *reinterpret_cast<const float4*>(&d_x1[off]);
            float r[4];
            #pragma unroll
            for (int k = 0; k < 4; k++) {
                float lg = a[ii][k];
                float sg = __fdividef(1.0f, 1.0f + __expf(-lg));
                r[k] = g * lg + (1.0f - g) * sg;
            }
            float4 res = make_float4(xr.x + r[0], xr.y + r[1], xr.z + r[2], xr.w + r[3]);
            *reinterpret_cast<float4*>(&out[off]) = res;
        }
    }
}

// ---------------------------------------------------------------------------
extern "C" void kernel_launch(void* const* d_in, const int* in_sizes, int n_in,
                              void* d_out, int out_size) {
    (void)in_sizes; (void)n_in; (void)out_size;
    const float* x      = (const float*)d_in[0];
    const float* n1g    = (const float*)d_in[1];
    const float* n1b    = (const float*)d_in[2];
    const float* qkv_w  = (const float*)d_in[3];
    const float* qkv_b  = (const float*)d_in[4];
    const float* proj_w = (const float*)d_in[5];
    const float* proj_b = (const float*)d_in[6];
    const float* n2g    = (const float*)d_in[7];
    const float* n2b    = (const float*)d_in[8];
    const float* nfg    = (const float*)d_in[9];
    const float* nfb    = (const float*)d_in[10];
    const float* pin_w  = (const float*)d_in[11];
    const float* pin_b  = (const float*)d_in[12];
    const float* tm_inc = (const float*)d_in[13];
    const float* tm_out = (const float*)d_in[14];
    const float* gate   = (const float*)d_in[15];
    float* out = (float*)d_out;

    cudaFuncSetAttribute(attn_kernel, cudaFuncAttributeMaxDynamicSharedMemorySize, ATTN_SMEM);
    cudaFuncSetAttribute(ffn_kernel,  cudaFuncAttributeMaxDynamicSharedMemorySize, FFN_SMEM);

    prep_kernel<<<336, 256>>>(tm_inc, pin_w, qkv_w, proj_w);
    attn_kernel<<<BB * 64, 256, ATTN_SMEM>>>(x, n1g, n1b, qkv_b, proj_b);
    ffn_kernel<<<NTOT / NTOK, 256, FFN_SMEM>>>(n2g, n2b, nfg, nfb, pin_b,
                                               tm_out, gate, out);
}

// round 14
// speedup vs baseline: 1.4798x; 1.3078x over previous
#include <cuda_runtime.h>
#include <cuda_bf16.h>
#include <math.h>
#include <stdint.h>

// Problem constants
#define BB   16
#define HH   56
#define WW   56
#define CC   96
#define LL_  3136        // 56*56
#define NHD  3
#define WS_  7
#define TT   49
#define HID_ 384
#define NCL_ 128
#define TWOH 768
#define NTOT (BB * LL_)  // 50176 tokens

#define LOG_EPS -13.815511f   // log(1e-6)

// ---------------------------------------------------------------------------
// device-global scratch (no allocation allowed)
// ---------------------------------------------------------------------------
__device__ float d_x1[NTOT * CC];                  // residual after attention
__device__ uint4 d_maskF[12 * 4 * 8 * 32];         // pre-fragmented mask B ops
__device__ uint4 d_pinF[6 * 6 * 2 * 4 * 32];       // pre-fragmented pin B ops (hi/lo)
__device__ float d_qkvT[CC * 288];                 // qkv_w^T [c][o]
__device__ float d_projT[CC * CC];                 // proj_w^T [c][o]

// ---------------------------------------------------------------------------
// helpers
// ---------------------------------------------------------------------------
__device__ __forceinline__ uint32_t smem_u32(const void* p) {
    uint32_t a;
    asm("{ .reg .u64 t; cvta.to.shared.u64 t, %1; cvt.u32.u64 %0, t; }" : "=r"(a) : "l"(p));
    return a;
}

#define LDMX4(r, a) \
    asm volatile("ldmatrix.sync.aligned.m8n8.x4.shared.b16 {%0,%1,%2,%3}, [%4];" \
                 : "=r"((r)[0]), "=r"((r)[1]), "=r"((r)[2]), "=r"((r)[3]) : "r"(a))

__device__ __forceinline__ void mma16816(float* d, const uint32_t* a,
                                         uint32_t b0, uint32_t b1) {
    asm volatile(
        "mma.sync.aligned.m16n8k16.row.col.f32.bf16.bf16.f32 "
        "{%0,%1,%2,%3}, {%4,%5,%6,%7}, {%8,%9}, {%0,%1,%2,%3};"
        : "+f"(d[0]), "+f"(d[1]), "+f"(d[2]), "+f"(d[3])
        : "r"(a[0]), "r"(a[1]), "r"(a[2]), "r"(a[3]), "r"(b0), "r"(b1));
}

__device__ __forceinline__ unsigned bmask_bits(float v) {
    return v > 0.0f ? 0x3F80u : 0u;   // bf16 1.0 / 0.0
}

__device__ __forceinline__ unsigned short bfh(float f) {
    return __bfloat16_as_ushort(__float2bfloat16(f));
}

// ---------------------------------------------------------------------------
// Prep: pre-fragment mask + pin weights (hi/lo); transpose attn weights.
// ---------------------------------------------------------------------------
__global__ void prep_kernel(const float* __restrict__ tm_inc,
                            const float* __restrict__ pin_w,
                            const float* __restrict__ qkv_w,
                            const float* __restrict__ proj_w) {
    int i = blockIdx.x * 256 + threadIdx.x;
    if (i < 12288) {
        int lane = i & 31, ntp = (i >> 5) & 7, ks = (i >> 8) & 3, ch = i >> 10;
        int qr = lane >> 2;
        int k  = ch * 64 + ks * 16 + (lane & 3) * 2;
        int n0 = ntp * 16 + qr, n1 = n0 + 8;
        const float* p0 = tm_inc + n0 * TWOH;
        const float* p1 = tm_inc + n1 * TWOH;
        uint4 u;
        u.x = bmask_bits(p0[k])     | (bmask_bits(p0[k + 1]) << 16);
        u.y = bmask_bits(p0[k + 8]) | (bmask_bits(p0[k + 9]) << 16);
        u.z = bmask_bits(p1[k])     | (bmask_bits(p1[k + 1]) << 16);
        u.w = bmask_bits(p1[k + 8]) | (bmask_bits(p1[k + 9]) << 16);
        d_maskF[i] = u;
        return;
    }
    i -= 12288;
    if (i < 9216) {
        // pinF[hc][ks(6)][hh2(2)][nt(4)][lane(32)]: hi b0,b1 | lo b0,b1
        int lane = i & 31; int j = i >> 5;
        int nt = j & 3; j >>= 2;
        int hh2 = j & 1; j >>= 1;
        int ks = j % 6; int hc = j / 6;
        int qr = lane >> 2;
        int n = hc * 64 + hh2 * 32 + nt * 8 + qr;
        int k = ks * 16 + (lane & 3) * 2;
        const float* p = pin_w + n * CC + k;
        float w0 = p[0], w1 = p[1], w8 = p[8], w9 = p[9];
        unsigned short h0 = bfh(w0), h1 = bfh(w1), h8 = bfh(w8), h9 = bfh(w9);
        unsigned short l0 = bfh(w0 - __bfloat162float(__ushort_as_bfloat16(h0)));
        unsigned short l1 = bfh(w1 - __bfloat162float(__ushort_as_bfloat16(h1)));
        unsigned short l8 = bfh(w8 - __bfloat162float(__ushort_as_bfloat16(h8)));
        unsigned short l9 = bfh(w9 - __bfloat162float(__ushort_as_bfloat16(h9)));
        uint4 u;
        u.x = (unsigned)h0 | ((unsigned)h1 << 16);
        u.y = (unsigned)h8 | ((unsigned)h9 << 16);
        u.z = (unsigned)l0 | ((unsigned)l1 << 16);
        u.w = (unsigned)l8 | ((unsigned)l9 << 16);
        d_pinF[i] = u;
        return;
    }
    i -= 9216;
    if (i < 288 * CC) {
        int o = i / CC, c = i - o * CC;
        d_qkvT[c * 288 + o] = qkv_w[i];
        return;
    }
    i -= 288 * CC;
    if (i < CC * CC) {
        int o = i / CC, c = i - o * CC;
        d_projT[c * CC + o] = proj_w[i];
    }
}

// ---------------------------------------------------------------------------
// Kernel 1: fused window attention (unchanged — 4x4 register tiles)
// ---------------------------------------------------------------------------
#define TP 52
#define AT_SZ  (96 * TP)
#define QT_SZ  (96 * TP)
#define KT_SZ  (96 * TP)
#define V_STR  100
#define V_SZ   (TP * V_STR)
#define S3_SZ  (3 * 49 * 49)
#define ATTN_SMEM ((AT_SZ + QT_SZ + KT_SZ + V_SZ + S3_SZ) * 4)

__global__ __launch_bounds__(256)
void attn_kernel(const float* __restrict__ x,
                 const float* __restrict__ n1g, const float* __restrict__ n1b,
                 const float* __restrict__ qkv_b,
                 const float* __restrict__ proj_b) {
    extern __shared__ float sm[];
    float* AT = sm;
    float* QT = AT + AT_SZ;
    float* KT = QT + QT_SZ;
    float* V  = KT + KT_SZ;
    float* S3 = V + V_SZ;

    const int tid  = threadIdx.x;
    const int lane = tid & 31;
    const int warp = tid >> 5;
    const int bw = blockIdx.x;
    const int b  = bw >> 6;
    const int wi = (bw >> 3) & 7;
    const int wj = bw & 7;

    for (int t = warp; t < TT; t += 8) {
        int ti = t / WS_, tj = t - ti * WS_;
        int r = (wi * WS_ + ti + 3) % HH;
        int c = (wj * WS_ + tj + 3) % WW;
        const float* row = x + ((size_t)(b * LL_ + r * WW + c)) * CC;
        float v0 = row[lane], v1 = row[lane + 32], v2 = row[lane + 64];
        float s = v0 + v1 + v2;
        #pragma unroll
        for (int o = 16; o; o >>= 1) s += __shfl_xor_sync(~0u, s, o);
        float m = s * (1.0f / 96.0f);
        float d0 = v0 - m, d1 = v1 - m, d2 = v2 - m;
        float vv = d0 * d0 + d1 * d1 + d2 * d2;
        #pragma unroll
        for (int o = 16; o; o >>= 1) vv += __shfl_xor_sync(~0u, vv, o);
        float inv = rsqrtf(vv * (1.0f / 96.0f) + 1e-5f);
        AT[lane * TP + t]        = d0 * inv * n1g[lane]      + n1b[lane];
        AT[(lane + 32) * TP + t] = d1 * inv * n1g[lane + 32] + n1b[lane + 32];
        AT[(lane + 64) * TP + t] = d2 * inv * n1g[lane + 64] + n1b[lane + 64];
    }
    __syncthreads();

    for (int idx = tid; idx < 13 * 72; idx += 256) {
        int og = idx % 72, tg = idx / 72;
        int o = og * 4;
        float a[4][4];
        #pragma unroll
        for (int ii = 0; ii < 4; ii++)
            #pragma unroll
            for (int k = 0; k < 4; k++) a[ii][k] = 0.0f;
        const float* atb = &AT[tg * 4];
        #pragma unroll 4
        for (int c = 0; c < CC; c++) {
            float4 av = *reinterpret_cast<const float4*>(&atb[c * TP]);
            float4 wv = *reinterpret_cast<const float4*>(&d_qkvT[c * 288 + o]);
            float avv[4] = {av.x, av.y, av.z, av.w};
            float wvv[4] = {wv.x, wv.y, wv.z, wv.w};
            #pragma unroll
            for (int ii = 0; ii < 4; ii++)
                #pragma unroll
                for (int k = 0; k < 4; k++) a[ii][k] += avv[ii] * wvv[k];
        }
        #pragma unroll
        for (int k = 0; k < 4; k++) {
            int ok = o + k;
            float bias = qkv_b[ok];
            #pragma unroll
            for (int ii = 0; ii < 4; ii++) {
                int t = tg * 4 + ii;
                float v = a[ii][k] + bias;
                if (ok < 96)       QT[ok * TP + t] = v;
                else if (ok < 192) KT[(ok - 96) * TP + t] = v;
                else               V[t * V_STR + (ok - 192)] = v;
            }
        }
    }
    __syncthreads();

    for (int idx = tid; idx < 507; idx += 256) {
        int h = idx / 169; int r = idx - h * 169;
        int ig = r / 13, jg = r - (r / 13) * 13;
        float a[4][4];
        #pragma unroll
        for (int ii = 0; ii < 4; ii++)
            #pragma unroll
            for (int jj = 0; jj < 4; jj++) a[ii][jj] = 0.0f;
        const float* qb = &QT[h * 32 * TP + ig * 4];
        const float* kb = &KT[h * 32 * TP + jg * 4];
        #pragma unroll 8
        for (int d = 0; d < 32; d++) {
            float4 qv = *reinterpret_cast<const float4*>(&qb[d * TP]);
            float4 kv = *reinterpret_cast<const float4*>(&kb[d * TP]);
            float qq[4] = {qv.x, qv.y, qv.z, qv.w};
            float kk[4] = {kv.x, kv.y, kv.z, kv.w};
            #pragma unroll
            for (int ii = 0; ii < 4; ii++)
                #pragma unroll
                for (int jj = 0; jj < 4; jj++) a[ii][jj] += qq[ii] * kk[jj];
        }
        #pragma unroll
        for (int ii = 0; ii < 4; ii++) {
            int i = ig * 4 + ii;
            if (i < TT) {
                #pragma unroll
                for (int jj = 0; jj < 4; jj++) {
                    int j = jg * 4 + jj;
                    if (j < TT)
                        S3[h * (TT * TT) + i * TT + j] = a[ii][jj] * 0.17677669529663687f;
                }
            }
        }
    }
    __syncthreads();

    for (int row = warp; row < 3 * TT; row += 8) {
        float* Sr = &S3[row * TT];
        float a0 = Sr[lane];
        float a1 = (lane < 17) ? Sr[32 + lane] : -1e30f;
        float mx = fmaxf(a0, a1);
        #pragma unroll
        for (int o = 16; o; o >>= 1) mx = fmaxf(mx, __shfl_xor_sync(~0u, mx, o));
        float e0 = __expf(a0 - mx);
        float e1 = (lane < 17) ? __expf(a1 - mx) : 0.0f;
        float ss = e0 + e1;
        #pragma unroll
        for (int o = 16; o; o >>= 1) ss += __shfl_xor_sync(~0u, ss, o);
        float inv = __fdividef(1.0f, ss);
        Sr[lane] = e0 * inv;
        if (lane < 17) Sr[32 + lane] = e1 * inv;
    }
    __syncthreads();

    for (int idx = tid; idx < 312; idx += 256) {
        int h = idx / 104; int r = idx - h * 104;
        int ig = r >> 3, dg = r & 7;
        float a[4][4];
        #pragma unroll
        for (int ii = 0; ii < 4; ii++)
            #pragma unroll
            for (int k = 0; k < 4; k++) a[ii][k] = 0.0f;
        const float* S0 = &S3[h * (TT * TT) + min(ig * 4 + 0, 48) * TT];
        const float* S1 = &S3[h * (TT * TT) + min(ig * 4 + 1, 48) * TT];
        const float* S2 = &S3[h * (TT * TT) + min(ig * 4 + 2, 48) * TT];
        const float* Sx = &S3[h * (TT * TT) + min(ig * 4 + 3, 48) * TT];
        const float* Vb = &V[h * 32 + dg * 4];
        #pragma unroll 7
        for (int j = 0; j < TT; j++) {
            float4 vv = *reinterpret_cast<const float4*>(&Vb[j * V_STR]);
            float vvv[4] = {vv.x, vv.y, vv.z, vv.w};
            float ss[4] = {S0[j], S1[j], S2[j], Sx[j]};
            #pragma unroll
            for (int ii = 0; ii < 4; ii++)
                #pragma unroll
                for (int k = 0; k < 4; k++) a[ii][k] += ss[ii] * vvv[k];
        }
        #pragma unroll
        for (int k = 0; k < 4; k++)
            #pragma unroll
            for (int ii = 0; ii < 4; ii++)
                AT[(h * 32 + dg * 4 + k) * TP + ig * 4 + ii] = a[ii][k];
    }
    __syncthreads();

    for (int idx = tid; idx < 312; idx += 256) {
        int tg = idx % 13, cg = idx / 13;
        int co = cg * 4;
        float a[4][4];
        #pragma unroll
        for (int ii = 0; ii < 4; ii++)
            #pragma unroll
            for (int k = 0; k < 4; k++) a[ii][k] = 0.0f;
        const float* atb = &AT[tg * 4];
        #pragma unroll 4
        for (int c = 0; c < CC; c++) {
            float4 ov = *reinterpret_cast<const float4*>(&atb[c * TP]);
            float4 wv = *reinterpret_cast<const float4*>(&d_projT[c * CC + co]);
            float oo[4] = {ov.x, ov.y, ov.z, ov.w};
            float ww[4] = {wv.x, wv.y, wv.z, wv.w};
            #pragma unroll
            for (int ii = 0; ii < 4; ii++)
                #pragma unroll
                for (int k = 0; k < 4; k++) a[ii][k] += oo[ii] * ww[k];
        }
        #pragma unroll
        for (int ii = 0; ii < 4; ii++) {
            int t = tg * 4 + ii;
            if (t < TT) {
                int ti = t / WS_, tj = t - ti * WS_;
                int dr = wi * WS_ + (ti + 3) % WS_;
                int dc = wj * WS_ + (tj + 3) % WS_;
                size_t off = ((size_t)(b * LL_ + dr * WW + dc)) * CC + co;
                float4 xr = *reinterpret_cast<const float4*>(&x[off]);
                float4 res = make_float4(xr.x + a[ii][0] + proj_b[co],
                                         xr.y + a[ii][1] + proj_b[co + 1],
                                         xr.z + a[ii][2] + proj_b[co + 2],
                                         xr.w + a[ii][3] + proj_b[co + 3]);
                *reinterpret_cast<float4*>(&d_x1[off]) = res;
            }
        }
    }
}

// ---------------------------------------------------------------------------
// Kernel 2: FUSED TM-FFN, all GEMMs except tm_out on tensor pipe.
// 64 tokens / CTA (784 CTAs), 256 threads (8 warps).
// LN -> W bf16 hi/lo smem. Per 64-hidden chunk hc (6):
//   pin MMA (3-product hi/lo split, B frags from d_pinF) -> softplus on
//   accumulator frags -> loglit hi/lo staging -> clause MMA (chunks hc, hc+6).
// Epilogue: exp -> CLT -> fp32 tm_out GEMM -> gated blend + residual.
// ---------------------------------------------------------------------------
#define NTOK 64
#define WROW 208                            // 96 bf16 + 16B pad
#define WH_OFF 0
#define WL_OFF (64 * WROW)                  // 13312
#define LLOFF  (2 * 64 * WROW)              // 26624
#define LL_ROW 144
#define LLB    (64 * LL_ROW)                // 9216
#define CLT_STR 68
#define FFN_SMEM (LLOFF + 4 * LLB)          // 63488; CLT (34816) overlays

__global__ __launch_bounds__(256)
void ffn_kernel(const float* __restrict__ n2g, const float* __restrict__ n2b,
                const float* __restrict__ nfg, const float* __restrict__ nfb,
                const float* __restrict__ pin_b,
                const float* __restrict__ tm_out,
                const float* __restrict__ gate,
                float* __restrict__ out) {
    extern __shared__ char smc[];
    const uint32_t sb = smem_u32(smc);
    float* CLT = reinterpret_cast<float*>(smc);

    const int tid  = threadIdx.x;
    const int wid  = tid >> 5;
    const int lane = tid & 31;
    const int qr   = lane >> 2;
    const int qc   = (lane & 3) * 2;
    const int t0   = blockIdx.x * NTOK;
    const int r0   = (wid >> 1) * 16;       // token rows for both MMAs
    const int ch2  = wid & 1;               // hidden half (pin) / clause half

    // --- 1. LN2 then LN_ffn -> W bf16 hi/lo [token][96ch] ---
    for (int tt = wid; tt < NTOK; tt += 8) {
        const float* row = d_x1 + (size_t)(t0 + tt) * CC;
        float v0 = row[lane], v1 = row[lane + 32], v2 = row[lane + 64];
        float s = v0 + v1 + v2;
        #pragma unroll
        for (int o = 16; o; o >>= 1) s += __shfl_xor_sync(~0u, s, o);
        float m = s * (1.0f / 96.0f);
        float d0 = v0 - m, d1 = v1 - m, d2 = v2 - m;
        float vv = d0 * d0 + d1 * d1 + d2 * d2;
        #pragma unroll
        for (int o = 16; o; o >>= 1) vv += __shfl_xor_sync(~0u, vv, o);
        float inv = rsqrtf(vv * (1.0f / 96.0f) + 1e-5f);
        float z0 = d0 * inv * n2g[lane]      + n2b[lane];
        float z1 = d1 * inv * n2g[lane + 32] + n2b[lane + 32];
        float z2 = d2 * inv * n2g[lane + 64] + n2b[lane + 64];
        float s2 = z0 + z1 + z2;
        #pragma unroll
        for (int o = 16; o; o >>= 1) s2 += __shfl_xor_sync(~0u, s2, o);
        float m2 = s2 * (1.0f / 96.0f);
        float e0 = z0 - m2, e1 = z1 - m2, e2 = z2 - m2;
        float v2s = e0 * e0 + e1 * e1 + e2 * e2;
        #pragma unroll
        for (int o = 16; o; o >>= 1) v2s += __shfl_xor_sync(~0u, v2s, o);
        float inv2 = rsqrtf(v2s * (1.0f / 96.0f) + 1e-5f);
        float w0 = e0 * inv2 * nfg[lane]      + nfb[lane];
        float w1 = e1 * inv2 * nfg[lane + 32] + nfb[lane + 32];
        float w2 = e2 * inv2 * nfg[lane + 64] + nfb[lane + 64];
        unsigned short wh0 = bfh(w0), wh1 = bfh(w1), wh2 = bfh(w2);
        unsigned short wl0 = bfh(w0 - __bfloat162float(__ushort_as_bfloat16(wh0)));
        unsigned short wl1 = bfh(w1 - __bfloat162float(__ushort_as_bfloat16(wh1)));
        unsigned short wl2 = bfh(w2 - __bfloat162float(__ushort_as_bfloat16(wh2)));
        unsigned short* ph = reinterpret_cast<unsigned short*>(smc + WH_OFF + tt * WROW);
        unsigned short* pl = reinterpret_cast<unsigned short*>(smc + WL_OFF + tt * WROW);
        ph[lane] = wh0; ph[lane + 32] = wh1; ph[lane + 64] = wh2;
        pl[lane] = wl0; pl[lane + 32] = wl1; pl[lane + 64] = wl2;
    }
    __syncthreads();

    float acc[32];
    #pragma unroll
    for (int i = 0; i < 32; i++) acc[i] = 0.0f;

    const uint32_t wfrag  = sb + (r0 + (lane & 15)) * WROW + (lane >> 4) * 16;
    const uint32_t llfrag = sb + LLOFF + (r0 + (lane & 15)) * LL_ROW + (lane >> 4) * 16;

    #pragma unroll 1
    for (int hc = 0; hc < 6; hc++) {
        // --- 2a. pin MMA: 16 tok x 32 hid (this warp) over K=96, split 3x ---
        float accp[16];
        #pragma unroll
        for (int i = 0; i < 16; i++) accp[i] = 0.0f;
        #pragma unroll
        for (int ks = 0; ks < 6; ks++) {
            uint32_t ah[4], al[4];
            LDMX4(ah, wfrag + ks * 32);
            LDMX4(al, wfrag + WL_OFF + ks * 32);
            const uint4* __restrict__ pf =
                d_pinF + (((hc * 6 + ks) * 2 + ch2) * 4) * 32 + lane;
            #pragma unroll
            for (int nt = 0; nt < 4; nt++) {
                uint4 b = pf[nt * 32];
                mma16816(&accp[nt * 4], ah, b.x, b.y);  // hi*hi
                mma16816(&accp[nt * 4], ah, b.z, b.w);  // hi*lo
                mma16816(&accp[nt * 4], al, b.x, b.y);  // lo*hi
            }
        }

        // --- 2b. softplus on frags -> loglit hi/lo staging ---
        #pragma unroll
        for (int nt = 0; nt < 4; nt++) {
            int hcol = ch2 * 32 + nt * 8 + qc;
            int habs = hc * 64 + hcol;
            float b0 = pin_b[habs], b1 = pin_b[habs + 1];
            #pragma unroll
            for (int rr = 0; rr < 2; rr++) {
                float v0 = accp[nt * 4 + rr * 2 + 0] + b0;
                float v1 = accp[nt * 4 + rr * 2 + 1] + b1;
                float u0 = __logf(1.0f + __expf(-fabsf(v0)));
                float u1 = __logf(1.0f + __expf(-fabsf(v1)));
                float lp0 = fmaxf(-(u0 + fmaxf(-v0, 0.0f)), LOG_EPS);
                float ln0 = fmaxf(-(u0 + fmaxf( v0, 0.0f)), LOG_EPS);
                float lp1 = fmaxf(-(u1 + fmaxf(-v1, 0.0f)), LOG_EPS);
                float ln1 = fmaxf(-(u1 + fmaxf( v1, 0.0f)), LOG_EPS);
                unsigned short ph0 = bfh(lp0), ph1 = bfh(lp1);
                unsigned short nh0 = bfh(ln0), nh1 = bfh(ln1);
                unsigned short pl0 = bfh(lp0 - __bfloat162float(__ushort_as_bfloat16(ph0)));
                unsigned short pl1 = bfh(lp1 - __bfloat162float(__ushort_as_bfloat16(ph1)));
                unsigned short nl0 = bfh(ln0 - __bfloat162float(__ushort_as_bfloat16(nh0)));
                unsigned short nl1 = bfh(ln1 - __bfloat162float(__ushort_as_bfloat16(nh1)));
                int r = r0 + qr + rr * 8;
                char* dst = smc + LLOFF + r * LL_ROW + hcol * 2;
                *reinterpret_cast<uint32_t*>(dst) =
                    (unsigned)ph0 | ((unsigned)ph1 << 16);
                *reinterpret_cast<uint32_t*>(dst + LLB) =
                    (unsigned)pl0 | ((unsigned)pl1 << 16);
                *reinterpret_cast<uint32_t*>(dst + 2 * LLB) =
                    (unsigned)nh0 | ((unsigned)nh1 << 16);
                *reinterpret_cast<uint32_t*>(dst + 3 * LLB) =
                    (unsigned)nl0 | ((unsigned)nl1 << 16);
            }
        }
        __syncthreads();

        // --- 2c. clause MMA for K-chunks hc (pos) and hc+6 (neg) ---
        #pragma unroll
        for (int part = 0; part < 2; part++) {
            const uint32_t hibase = llfrag + part * 2 * LLB;
            const int ch = hc + part * 6;
            #pragma unroll
            for (int ks = 0; ks < 4; ks++) {
                uint32_t ah[4], al[4];
                uint32_t addr = hibase + ks * 32;
                LDMX4(ah, addr);
                LDMX4(al, addr + LLB);
                const uint4* __restrict__ mf =
                    d_maskF + ((ch * 4 + ks) * 8 + ch2 * 4) * 32 + lane;
                #pragma unroll
                for (int ntp = 0; ntp < 4; ntp++) {
                    uint4 b = mf[ntp * 32];
                    mma16816(&acc[(2 * ntp) * 4],     ah, b.x, b.y);
                    mma16816(&acc[(2 * ntp) * 4],     al, b.x, b.y);
                    mma16816(&acc[(2 * ntp + 1) * 4], ah, b.z, b.w);
                    mma16816(&acc[(2 * ntp + 1) * 4], al, b.z, b.w);
                }
            }
        }
        __syncthreads();
    }

    // --- 3. exp + transposed store: CLT[j][t_local] (overlays W/LL) ---
    #pragma unroll
    for (int nt = 0; nt < 8; nt++) {
        int j = ch2 * 64 + nt * 8 + qc;
        CLT[j * CLT_STR + r0 + qr]           = __expf(acc[nt * 4 + 0]);
        CLT[(j + 1) * CLT_STR + r0 + qr]     = __expf(acc[nt * 4 + 1]);
        CLT[j * CLT_STR + r0 + qr + 8]       = __expf(acc[nt * 4 + 2]);
        CLT[(j + 1) * CLT_STR + r0 + qr + 8] = __expf(acc[nt * 4 + 3]);
    }
    __syncthreads();

    // --- 4. logits = clauses @ tm_out; gated blend + residual ---
    const float g = __fdividef(1.0f, 1.0f + __expf(-gate[0]));
    for (int idx = tid; idx < 16 * 24; idx += 256) {
        int tg = idx & 15, cg = idx >> 4;
        float a[4][4];
        #pragma unroll
        for (int ii = 0; ii < 4; ii++)
            #pragma unroll
            for (int k = 0; k < 4; k++) a[ii][k] = 0.0f;
        const float* clb = &CLT[tg * 4];
        const float* ob  = &tm_out[cg * 4];
        #pragma unroll 8
        for (int j = 0; j < NCL_; j++) {
            float4 cv = *reinterpret_cast<const float4*>(&clb[j * CLT_STR]);
            float4 ov = *reinterpret_cast<const float4*>(&ob[j * CC]);
            float cc[4] = {cv.x, cv.y, cv.z, cv.w};
            float oo[4] = {ov.x, ov.y, ov.z, ov.w};
            #pragma unroll
            for (int ii = 0; ii < 4; ii++)
                #pragma unroll
                for (int k = 0; k < 4; k++) a[ii][k] += cc[ii] * oo[k];
        }
        #pragma unroll
        for (int ii = 0; ii < 4; ii++) {
            size_t off = (size_t)(t0 + tg * 4 + ii) * CC + cg * 4;
            float4 xr = *reinterpret_cast<const float4*>(&d_x1[off]);
            float r[4];
            #pragma unroll
            for (int k = 0; k < 4; k++) {
                float lg = a[ii][k];
                float sg = __fdividef(1.0f, 1.0f + __expf(-lg));
                r[k] = g * lg + (1.0f - g) * sg;
            }
            float4 res = make_float4(xr.x + r[0], xr.y + r[1], xr.z + r[2], xr.w + r[3]);
            *reinterpret_cast<float4*>(&out[off]) = res;
        }
    }
}

// ---------------------------------------------------------------------------
extern "C" void kernel_launch(void* const* d_in, const int* in_sizes, int n_in,
                              void* d_out, int out_size) {
    (void)in_sizes; (void)n_in; (void)out_size;
    const float* x      = (const float*)d_in[0];
    const float* n1g    = (const float*)d_in[1];
    const float* n1b    = (const float*)d_in[2];
    const float* qkv_w  = (const float*)d_in[3];
    const float* qkv_b  = (const float*)d_in[4];
    const float* proj_w = (const float*)d_in[5];
    const float* proj_b = (const float*)d_in[6];
    const float* n2g    = (const float*)d_in[7];
    const float* n2b    = (const float*)d_in[8];
    const float* nfg    = (const float*)d_in[9];
    const float* nfb    = (const float*)d_in[10];
    const float* pin_w  = (const float*)d_in[11];
    const float* pin_b  = (const float*)d_in[12];
    const float* tm_inc = (const float*)d_in[13];
    const float* tm_out = (const float*)d_in[14];
    const float* gate   = (const float*)d_in[15];
    float* out = (float*)d_out;

    cudaFuncSetAttribute(attn_kernel, cudaFuncAttributeMaxDynamicSharedMemorySize, ATTN_SMEM);
    cudaFuncSetAttribute(ffn_kernel,  cudaFuncAttributeMaxDynamicSharedMemorySize, FFN_SMEM);

    // prep covers 12288 + 9216 + 27648 + 9216 = 58368 = 228 * 256
    prep_kernel<<<228, 256>>>(tm_inc, pin_w, qkv_w, proj_w);
    attn_kernel<<<BB * 64, 256, ATTN_SMEM>>>(x, n1g, n1b, qkv_b, proj_b);
    ffn_kernel<<<NTOT / NTOK, 256, FFN_SMEM>>>(n2g, n2b, nfg, nfb, pin_b,
                                               tm_out, gate, out);
}